// round 1
// baseline (speedup 1.0000x reference)
#include <cuda_runtime.h>
#include <cuda_bf16.h>

// Problem constants (fixed shapes for GLiNERLinkerPooler_14671608283278)
#define L_TOK 2048
#define H_DIM 768
#define W_NUM 1024
#define C_NUM 64
#define TH_DIM 1536   // 2*H
// W1 is (2304, 768): rows [0,768)=W1_t, [768,1536)=W1_l, [1536,2304)=W1_p

// ---------------- device scratch (no allocations allowed) ----------------
__device__ int   g_winner[W_NUM];
__device__ float g_we[W_NUM * H_DIM];          // 3 MB
__device__ float g_t [W_NUM * TH_DIM];         // 6.3 MB
__device__ float g_lb[C_NUM * TH_DIM];         // 0.4 MB
__device__ float g_At[W_NUM * H_DIM];          // 3 MB  (t0@W1_t + b1)
__device__ float g_Al[C_NUM * H_DIM];          // 0.2 MB (lb0@W1_l)

// ---------------- step 1: winner per word (last token index wins) --------
__global__ void k_init_winner() {
    int w = blockIdx.x * blockDim.x + threadIdx.x;
    if (w < W_NUM) g_winner[w] = -1;
}

__global__ void k_scatter(const int* __restrict__ wmask) {
    int l = blockIdx.x * blockDim.x + threadIdx.x;
    if (l < L_TOK) {
        int v = wmask[l];
        if (v > 0 && v - 1 < W_NUM) atomicMax(&g_winner[v - 1], l);
    }
}

__global__ void k_build_we(const float* __restrict__ tok_embs) {
    int w = blockIdx.x;
    int src = g_winner[w];
    float* dst = &g_we[w * H_DIM];
    if (src >= 0) {
        const float* s = &tok_embs[src * H_DIM];
        for (int h = threadIdx.x; h < H_DIM; h += blockDim.x) dst[h] = s[h];
    } else {
        for (int h = threadIdx.x; h < H_DIM; h += blockDim.x) dst[h] = 0.0f;
    }
}

// ---------------- generic tiled fp32 GEMM: C = A@B (+bias) ---------------
// A: (M,K) row-major w/ leading dim lda ; B: (K,N) row-major w/ ldb ;
// C: (M,N) w/ ldc. Grid: (M/64, N/64), block 256, 4x4 microtile, BK=16.
// All dims are multiples of tile sizes in this problem.
__global__ void k_gemm_bias(const float* __restrict__ A, int lda,
                            const float* __restrict__ B, int ldb,
                            const float* __restrict__ bias,
                            float* __restrict__ C, int ldc, int K) {
    __shared__ float As[16][64];
    __shared__ float Bs[16][64];
    const int tid = threadIdx.x;
    const int tx = tid & 15;         // N direction (4 cols each)
    const int ty = tid >> 4;         // M direction (4 rows each)
    const int mbase = blockIdx.x * 64;
    const int nbase = blockIdx.y * 64;

    float acc[4][4] = {};

    const int lw = tid >> 2, lkq = tid & 3;    // A loader: row, k-quad
    const int lkk = tid >> 4, lj4 = tid & 15;  // B loader: k-row, col-quad

    for (int k0 = 0; k0 < K; k0 += 16) {
        float4 va = *reinterpret_cast<const float4*>(&A[(size_t)(mbase + lw) * lda + k0 + lkq * 4]);
        As[lkq * 4 + 0][lw] = va.x;
        As[lkq * 4 + 1][lw] = va.y;
        As[lkq * 4 + 2][lw] = va.z;
        As[lkq * 4 + 3][lw] = va.w;
        *reinterpret_cast<float4*>(&Bs[lkk][lj4 * 4]) =
            *reinterpret_cast<const float4*>(&B[(size_t)(k0 + lkk) * ldb + nbase + lj4 * 4]);
        __syncthreads();
#pragma unroll
        for (int kk = 0; kk < 16; kk++) {
            float4 a4 = *reinterpret_cast<const float4*>(&As[kk][ty * 4]);
            float4 b4 = *reinterpret_cast<const float4*>(&Bs[kk][tx * 4]);
            float a[4] = {a4.x, a4.y, a4.z, a4.w};
            float b[4] = {b4.x, b4.y, b4.z, b4.w};
#pragma unroll
            for (int i = 0; i < 4; i++)
#pragma unroll
                for (int j = 0; j < 4; j++)
                    acc[i][j] = fmaf(a[i], b[j], acc[i][j]);
        }
        __syncthreads();
    }
#pragma unroll
    for (int j = 0; j < 4; j++) {
        int col = nbase + tx * 4 + j;
        float bv = bias ? bias[col] : 0.0f;
#pragma unroll
        for (int i = 0; i < 4; i++) {
            int row = mbase + ty * 4 + i;
            C[(size_t)row * ldc + col] = acc[i][j] + bv;
        }
    }
}

// ---------------- main fused kernel ---------------------------------------
// For (w_tile, c): loop 12 j-tiles of 64:
//   P = t1[w_tile,:] @ (diag(lb1[c]) @ W1p[:, j_tile])    (K = 768)
//   h = relu(P + A_t[w, j] + A_l[c, j])                   (b1 inside A_t)
//   sc[w, k] += h[w, j] * W2[j, k]
// Reduce sc over the 16 j-threads (warp shuffle), write scores + b2.
__global__ void k_main_fused(const float* __restrict__ t,
                             const float* __restrict__ lb,
                             const float* __restrict__ At,
                             const float* __restrict__ Al,
                             const float* __restrict__ W1p,   // (768, 768)
                             const float* __restrict__ W2,    // (768, 3)
                             const float* __restrict__ b2,    // (3)
                             float* __restrict__ out) {       // (W, C, 3)
    __shared__ float As[16][64];
    __shared__ float Bs[16][64];
    __shared__ float lbs[H_DIM];

    const int tid = threadIdx.x;
    const int c = blockIdx.y;
    const int wbase = blockIdx.x * 64;
    const int tx = tid & 15;
    const int ty = tid >> 4;

    // preload lb1[c, :] = lb[c, 768 + k]
    for (int k = tid; k < H_DIM; k += 256) lbs[k] = lb[c * TH_DIM + H_DIM + k];
    __syncthreads();

    const int lw = tid >> 2, lkq = tid & 3;
    const int lkk = tid >> 4, lj4 = tid & 15;

    float sc[4][3] = {};

    for (int jt = 0; jt < 12; jt++) {
        const int jbase = jt * 64;
        float acc[4][4] = {};
        for (int k0 = 0; k0 < H_DIM; k0 += 16) {
            // A tile: t1 rows (stride 1536, col offset 768), scaled by lb1[c,k]
            float4 va = *reinterpret_cast<const float4*>(
                &t[(size_t)(wbase + lw) * TH_DIM + H_DIM + k0 + lkq * 4]);
            As[lkq * 4 + 0][lw] = va.x * lbs[k0 + lkq * 4 + 0];
            As[lkq * 4 + 1][lw] = va.y * lbs[k0 + lkq * 4 + 1];
            As[lkq * 4 + 2][lw] = va.z * lbs[k0 + lkq * 4 + 2];
            As[lkq * 4 + 3][lw] = va.w * lbs[k0 + lkq * 4 + 3];
            // B tile: W1p
            *reinterpret_cast<float4*>(&Bs[lkk][lj4 * 4]) =
                *reinterpret_cast<const float4*>(&W1p[(size_t)(k0 + lkk) * H_DIM + jbase + lj4 * 4]);
            __syncthreads();
#pragma unroll
            for (int kk = 0; kk < 16; kk++) {
                float4 a4 = *reinterpret_cast<const float4*>(&As[kk][ty * 4]);
                float4 b4 = *reinterpret_cast<const float4*>(&Bs[kk][tx * 4]);
                float a[4] = {a4.x, a4.y, a4.z, a4.w};
                float b[4] = {b4.x, b4.y, b4.z, b4.w};
#pragma unroll
                for (int i = 0; i < 4; i++)
#pragma unroll
                    for (int j = 0; j < 4; j++)
                        acc[i][j] = fmaf(a[i], b[j], acc[i][j]);
            }
            __syncthreads();
        }
        // epilogue for this j-tile
#pragma unroll
        for (int j = 0; j < 4; j++) {
            int col = jbase + tx * 4 + j;
            float al = Al[c * H_DIM + col];
            float w20 = W2[col * 3 + 0];
            float w21 = W2[col * 3 + 1];
            float w22 = W2[col * 3 + 2];
#pragma unroll
            for (int i = 0; i < 4; i++) {
                int row = wbase + ty * 4 + i;
                float h = acc[i][j] + At[(size_t)row * H_DIM + col] + al;
                h = fmaxf(h, 0.0f);
                sc[i][0] = fmaf(h, w20, sc[i][0]);
                sc[i][1] = fmaf(h, w21, sc[i][1]);
                sc[i][2] = fmaf(h, w22, sc[i][2]);
            }
        }
    }

    // reduce over tx (16 consecutive lanes per ty group; groups are
    // 16-lane-aligned inside the warp, so xor-1/2/4/8 stays in-group)
    float bb0 = b2[0], bb1 = b2[1], bb2 = b2[2];
#pragma unroll
    for (int i = 0; i < 4; i++) {
#pragma unroll
        for (int k = 0; k < 3; k++) {
            float v = sc[i][k];
            v += __shfl_xor_sync(0xffffffffu, v, 1);
            v += __shfl_xor_sync(0xffffffffu, v, 2);
            v += __shfl_xor_sync(0xffffffffu, v, 4);
            v += __shfl_xor_sync(0xffffffffu, v, 8);
            sc[i][k] = v;
        }
        if (tx == 0) {
            int row = wbase + ty * 4 + i;
            float* o = &out[(size_t)row * (C_NUM * 3) + c * 3];
            o[0] = sc[i][0] + bb0;
            o[1] = sc[i][1] + bb1;
            o[2] = sc[i][2] + bb2;
        }
    }
}

// ---------------- launch ---------------------------------------------------
extern "C" void kernel_launch(void* const* d_in, const int* in_sizes, int n_in,
                              void* d_out, int out_size) {
    const float* tok_embs   = (const float*)d_in[0];   // (2048, 768)
    const int*   wmask      = (const int*)  d_in[1];   // (2048,)
    // d_in[2] = text_length (scalar, value 1024) — shapes are fixed, unused
    const float* label_embs = (const float*)d_in[3];   // (64, 768)
    const float* W_tok      = (const float*)d_in[4];   // (768, 1536)
    const float* b_tok      = (const float*)d_in[5];   // (1536,)
    const float* W_lab      = (const float*)d_in[6];   // (768, 1536)
    const float* b_lab      = (const float*)d_in[7];   // (1536,)
    const float* W1         = (const float*)d_in[8];   // (2304, 768)
    const float* b1         = (const float*)d_in[9];   // (768,)
    const float* W2         = (const float*)d_in[10];  // (768, 3)
    const float* b2         = (const float*)d_in[11];  // (3,)
    float* out = (float*)d_out;                        // (1024, 64, 3)

    float *we, *t, *lbp, *At, *Al;
    cudaGetSymbolAddress((void**)&we,  g_we);
    cudaGetSymbolAddress((void**)&t,   g_t);
    cudaGetSymbolAddress((void**)&lbp, g_lb);
    cudaGetSymbolAddress((void**)&At,  g_At);
    cudaGetSymbolAddress((void**)&Al,  g_Al);

    // 1) scatter pooling (last token index wins per word)
    k_init_winner<<<(W_NUM + 255) / 256, 256>>>();
    k_scatter<<<(L_TOK + 255) / 256, 256>>>(wmask);
    k_build_we<<<W_NUM, 256>>>(tok_embs);

    // 2) t = we @ W_tok + b_tok          (1024 x 1536, K=768)
    k_gemm_bias<<<dim3(W_NUM / 64, TH_DIM / 64), 256>>>(
        we, H_DIM, W_tok, TH_DIM, b_tok, t, TH_DIM, H_DIM);

    // 3) lb = label_embs @ W_lab + b_lab (64 x 1536, K=768)
    k_gemm_bias<<<dim3(1, TH_DIM / 64), 256>>>(
        label_embs, H_DIM, W_lab, TH_DIM, b_lab, lbp, TH_DIM, H_DIM);

    // 4) A_t = t0 @ W1_t + b1            (1024 x 768)
    k_gemm_bias<<<dim3(W_NUM / 64, H_DIM / 64), 256>>>(
        t, TH_DIM, W1, H_DIM, b1, At, H_DIM, H_DIM);

    // 5) A_l = lb0 @ W1_l                (64 x 768)
    k_gemm_bias<<<dim3(1, H_DIM / 64), 256>>>(
        lbp, TH_DIM, W1 + (size_t)H_DIM * H_DIM, H_DIM, nullptr, Al, H_DIM, H_DIM);

    // 6) fused prod-GEMM + relu + W2 contraction -> scores
    k_main_fused<<<dim3(W_NUM / 64, C_NUM), 256>>>(
        t, lbp, At, Al, W1 + (size_t)2 * H_DIM * H_DIM, W2, b2, out);

    (void)in_sizes; (void)n_in; (void)out_size;
}

// round 5
// speedup vs baseline: 2.5839x; 2.5839x over previous
#include <cuda_runtime.h>
#include <cuda_bf16.h>
#include <cstdint>

// Problem constants (fixed shapes for GLiNERLinkerPooler_14671608283278)
#define L_TOK 2048
#define H_DIM 768
#define W_NUM 1024
#define C_NUM 64
#define TH_DIM 1536   // 2*H
// W1 is (2304, 768): rows [0,768)=W1_t, [768,1536)=W1_l, [1536,2304)=W1_p

// ---------------- device scratch (no allocations allowed) ----------------
__device__ int   g_winner[W_NUM];
__device__ float g_we[W_NUM * H_DIM];            // 3 MB
__device__ float g_t [W_NUM * TH_DIM];           // 6.3 MB
__device__ float g_lb[C_NUM * TH_DIM];           // 0.4 MB
__device__ float g_At[W_NUM * H_DIM];            // 3 MB  (t0@W1_t + b1)
__device__ float g_Al[C_NUM * H_DIM];            // 0.2 MB

// ---------------- helpers -------------------------------------------------
__device__ __forceinline__ float to_tf32(float x) {
    float r;
    asm("cvt.rna.tf32.f32 %0, %1;" : "=f"(r) : "f"(x));
    return r;
}
// m16n8k8 tf32 MMA (sm_80+ baseline PTX — no 'a'-arch features)
__device__ __forceinline__ void mma_tf32(float* c, const uint32_t* a,
                                         uint32_t b0, uint32_t b1) {
    asm volatile(
        "mma.sync.aligned.m16n8k8.row.col.f32.tf32.tf32.f32 "
        "{%0,%1,%2,%3}, {%4,%5,%6,%7}, {%8,%9}, {%0,%1,%2,%3};"
        : "+f"(c[0]), "+f"(c[1]), "+f"(c[2]), "+f"(c[3])
        : "r"(a[0]), "r"(a[1]), "r"(a[2]), "r"(a[3]), "r"(b0), "r"(b1));
}

// ---------------- step 1: winner per word (last token index wins) --------
__global__ void k_init_winner() {
    int w = blockIdx.x * blockDim.x + threadIdx.x;
    if (w < W_NUM) g_winner[w] = -1;
}
__global__ void k_scatter(const int* __restrict__ wmask) {
    int l = blockIdx.x * blockDim.x + threadIdx.x;
    if (l < L_TOK) {
        int v = wmask[l];
        if (v > 0 && v - 1 < W_NUM) atomicMax(&g_winner[v - 1], l);
    }
}
__global__ void k_build_we(const float* __restrict__ tok_embs) {
    int w = blockIdx.x;
    int src = g_winner[w];
    float* dst = &g_we[w * H_DIM];
    if (src >= 0) {
        const float* s = &tok_embs[src * H_DIM];
        for (int h = threadIdx.x; h < H_DIM; h += blockDim.x) dst[h] = s[h];
    } else {
        for (int h = threadIdx.x; h < H_DIM; h += blockDim.x) dst[h] = 0.0f;
    }
}

// ---------------- generic tiled fp32 GEMM: C = A@B (+bias) ---------------
__global__ void k_gemm_bias(const float* __restrict__ A, int lda,
                            const float* __restrict__ B, int ldb,
                            const float* __restrict__ bias,
                            float* __restrict__ C, int ldc, int K) {
    __shared__ float As[16][64];
    __shared__ float Bs[16][64];
    const int tid = threadIdx.x;
    const int tx = tid & 15;
    const int ty = tid >> 4;
    const int mbase = blockIdx.x * 64;
    const int nbase = blockIdx.y * 64;

    float acc[4][4] = {};
    const int lw = tid >> 2, lkq = tid & 3;
    const int lkk = tid >> 4, lj4 = tid & 15;

    for (int k0 = 0; k0 < K; k0 += 16) {
        float4 va = *reinterpret_cast<const float4*>(&A[(size_t)(mbase + lw) * lda + k0 + lkq * 4]);
        As[lkq * 4 + 0][lw] = va.x;
        As[lkq * 4 + 1][lw] = va.y;
        As[lkq * 4 + 2][lw] = va.z;
        As[lkq * 4 + 3][lw] = va.w;
        *reinterpret_cast<float4*>(&Bs[lkk][lj4 * 4]) =
            *reinterpret_cast<const float4*>(&B[(size_t)(k0 + lkk) * ldb + nbase + lj4 * 4]);
        __syncthreads();
#pragma unroll
        for (int kk = 0; kk < 16; kk++) {
            float4 a4 = *reinterpret_cast<const float4*>(&As[kk][ty * 4]);
            float4 b4 = *reinterpret_cast<const float4*>(&Bs[kk][tx * 4]);
            float a[4] = {a4.x, a4.y, a4.z, a4.w};
            float b[4] = {b4.x, b4.y, b4.z, b4.w};
#pragma unroll
            for (int i = 0; i < 4; i++)
#pragma unroll
                for (int j = 0; j < 4; j++)
                    acc[i][j] = fmaf(a[i], b[j], acc[i][j]);
        }
        __syncthreads();
    }
#pragma unroll
    for (int j = 0; j < 4; j++) {
        int col = nbase + tx * 4 + j;
        float bv = bias ? bias[col] : 0.0f;
#pragma unroll
        for (int i = 0; i < 4; i++) {
            int row = mbase + ty * 4 + i;
            C[(size_t)row * ldc + col] = acc[i][j] + bv;
        }
    }
}

// ================== main fused mma.sync tf32 kernel =======================
// Grid (8, 64). Block: 256 threads (8 warps, 4m x 2n), BM=128, BN=128,
// BK=32 double-buffered. P = (t1 * lb1[c]) @ W1p over K=768, then fused
// relu(P + At + Al) -> W2 contraction -> shfl + shared reduce -> scores.
#define BM 128
#define BN 128
#define BK 32
#define NJT 6               // 768 / BN
#define KTILES 24           // 768 / BK
#define LDA 36              // BK + 4 pad  (conflict-free frag loads)
#define LDB 136             // BN + 8 pad  (conflict-free frag loads)

#define F_AS   0                         // 2*128*36   = 9216 floats
#define F_BS   9216                      // 2*32*136   = 8704 floats
#define F_LBS  17920                     // 768
#define F_ALS  18688                     // 768
#define F_W2S  19456                     // 2304
#define F_SCR  21760                     // 384
#define SMEM_FLOATS 22144
#define SMEM_SZ (SMEM_FLOATS * 4)        // 88576 bytes

__global__ void __launch_bounds__(256)
k_main_mma(const float* __restrict__ t,
           const float* __restrict__ lb,
           const float* __restrict__ At,    // (1024, 768)
           const float* __restrict__ Al,    // (64, 768)
           const float* __restrict__ W1p,   // (768 h, 768 j)  natural [k][n]
           const float* __restrict__ W2,    // (768, 3)
           const float* __restrict__ b2,
           float* __restrict__ out) {       // (1024, 64, 3)
    extern __shared__ float sm[];
    float* As  = sm + F_AS;
    float* Bs  = sm + F_BS;
    float* lbs = sm + F_LBS;
    float* als = sm + F_ALS;
    float* w2s = sm + F_W2S;
    float* scr = sm + F_SCR;

    const int tid = threadIdx.x;
    const int lane = tid & 31, wid = tid >> 5;
    const int wm = wid & 3, wn = wid >> 2;
    const int qr = lane >> 2, qc = lane & 3;
    const int c = blockIdx.y;
    const int wbase = blockIdx.x * BM;

    for (int i = tid; i < H_DIM; i += 256) {
        lbs[i] = lb[c * TH_DIM + H_DIM + i];
        als[i] = Al[c * H_DIM + i];
    }
    for (int i = tid; i < 3 * H_DIM; i += 256) w2s[i] = W2[i];
    for (int i = tid; i < BM * 3; i += 256) scr[i] = 0.0f;
    __syncthreads();

    // loader thread mapping
    const int a_c8 = tid & 7;    // float4 slot within BK=32 (8 slots)
    const int a_r0 = tid >> 3;   // row base (0..31), rows r0 + 32*i
    const int b_c4 = tid & 31;   // float4 slot within BN=128 (32 slots)
    const int b_k0 = tid >> 5;   // k base (0..7), k = k0 + 8*i

    float sc[4][3];
#pragma unroll
    for (int i = 0; i < 4; i++)
#pragma unroll
        for (int k = 0; k < 3; k++) sc[i][k] = 0.0f;

    for (int jt = 0; jt < NJT; jt++) {
        const int jb = jt * BN;
        float cf[2][8][4];
#pragma unroll
        for (int mt = 0; mt < 2; mt++)
#pragma unroll
            for (int nt = 0; nt < 8; nt++)
#pragma unroll
                for (int r = 0; r < 4; r++) cf[mt][nt][r] = 0.0f;

        // ---- preload k-tile 0 into stage 0 ----
        {
            float* Ad = As;              // stage 0
            float* Bd = Bs;
            float4 sl = *reinterpret_cast<const float4*>(&lbs[a_c8 * 4]);
#pragma unroll
            for (int i = 0; i < 4; i++) {
                int row = a_r0 + 32 * i;
                float4 v = *reinterpret_cast<const float4*>(
                    &t[(wbase + row) * TH_DIM + H_DIM + a_c8 * 4]);
                v.x = to_tf32(v.x * sl.x); v.y = to_tf32(v.y * sl.y);
                v.z = to_tf32(v.z * sl.z); v.w = to_tf32(v.w * sl.w);
                *reinterpret_cast<float4*>(&Ad[row * LDA + a_c8 * 4]) = v;
            }
#pragma unroll
            for (int i = 0; i < 4; i++) {
                int k = b_k0 + 8 * i;
                float4 v = *reinterpret_cast<const float4*>(
                    &W1p[k * H_DIM + jb + b_c4 * 4]);
                v.x = to_tf32(v.x); v.y = to_tf32(v.y);
                v.z = to_tf32(v.z); v.w = to_tf32(v.w);
                *reinterpret_cast<float4*>(&Bd[k * LDB + b_c4 * 4]) = v;
            }
        }
        __syncthreads();

        for (int kt = 0; kt < KTILES; kt++) {
            const int s = kt & 1;
            // ---- stage next tile: LDG into regs now, STS after compute ----
            float4 rA[4], rB[4], sl;
            const bool more = (kt + 1 < KTILES);
            if (more) {
                const int k0 = (kt + 1) * BK;
                sl = *reinterpret_cast<const float4*>(&lbs[k0 + a_c8 * 4]);
#pragma unroll
                for (int i = 0; i < 4; i++) {
                    int row = a_r0 + 32 * i;
                    rA[i] = *reinterpret_cast<const float4*>(
                        &t[(wbase + row) * TH_DIM + H_DIM + k0 + a_c8 * 4]);
                }
#pragma unroll
                for (int i = 0; i < 4; i++) {
                    int k = b_k0 + 8 * i;
                    rB[i] = *reinterpret_cast<const float4*>(
                        &W1p[(k0 + k) * H_DIM + jb + b_c4 * 4]);
                }
            }
            // ---- compute on stage s ----
            const float* Asb = As + s * (BM * LDA);
            const float* Bsb = Bs + s * (BK * LDB);
#pragma unroll
            for (int k8 = 0; k8 < BK; k8 += 8) {
                uint32_t a[2][4];
#pragma unroll
                for (int mt = 0; mt < 2; mt++) {
                    int rb = wm * 32 + mt * 16 + qr;
                    a[mt][0] = __float_as_uint(Asb[rb * LDA + k8 + qc]);
                    a[mt][1] = __float_as_uint(Asb[(rb + 8) * LDA + k8 + qc]);
                    a[mt][2] = __float_as_uint(Asb[rb * LDA + k8 + qc + 4]);
                    a[mt][3] = __float_as_uint(Asb[(rb + 8) * LDA + k8 + qc + 4]);
                }
#pragma unroll
                for (int nt = 0; nt < 8; nt++) {
                    int ncol = wn * 64 + nt * 8 + qr;
                    uint32_t b0 = __float_as_uint(Bsb[(k8 + qc) * LDB + ncol]);
                    uint32_t b1 = __float_as_uint(Bsb[(k8 + qc + 4) * LDB + ncol]);
                    mma_tf32(cf[0][nt], a[0], b0, b1);
                    mma_tf32(cf[1][nt], a[1], b0, b1);
                }
            }
            // ---- store staged tile to the other buffer ----
            if (more) {
                float* Ad = As + (s ^ 1) * (BM * LDA);
                float* Bd = Bs + (s ^ 1) * (BK * LDB);
#pragma unroll
                for (int i = 0; i < 4; i++) {
                    int row = a_r0 + 32 * i;
                    float4 v = rA[i];
                    v.x = to_tf32(v.x * sl.x); v.y = to_tf32(v.y * sl.y);
                    v.z = to_tf32(v.z * sl.z); v.w = to_tf32(v.w * sl.w);
                    *reinterpret_cast<float4*>(&Ad[row * LDA + a_c8 * 4]) = v;
                }
#pragma unroll
                for (int i = 0; i < 4; i++) {
                    int k = b_k0 + 8 * i;
                    float4 v = rB[i];
                    v.x = to_tf32(v.x); v.y = to_tf32(v.y);
                    v.z = to_tf32(v.z); v.w = to_tf32(v.w);
                    *reinterpret_cast<float4*>(&Bd[k * LDB + b_c4 * 4]) = v;
                }
            }
            __syncthreads();
        }

        // ---- fused epilogue for this j-tile ----
#pragma unroll
        for (int mt = 0; mt < 2; mt++) {
#pragma unroll
            for (int nt = 0; nt < 8; nt++) {
                const int gcol = jb + wn * 64 + nt * 8 + 2 * qc;
                const int row0 = wbase + wm * 32 + mt * 16 + qr;
                float2 at0 = __ldg(reinterpret_cast<const float2*>(&At[row0 * H_DIM + gcol]));
                float2 at1 = __ldg(reinterpret_cast<const float2*>(&At[(row0 + 8) * H_DIM + gcol]));
                const float al0 = als[gcol], al1 = als[gcol + 1];
                const float wa0 = w2s[gcol * 3 + 0], wa1 = w2s[gcol * 3 + 1], wa2 = w2s[gcol * 3 + 2];
                const float wb0 = w2s[gcol * 3 + 3], wb1 = w2s[gcol * 3 + 4], wb2 = w2s[gcol * 3 + 5];
                const float h00 = fmaxf(cf[mt][nt][0] + at0.x + al0, 0.0f);
                const float h01 = fmaxf(cf[mt][nt][1] + at0.y + al1, 0.0f);
                const float h10 = fmaxf(cf[mt][nt][2] + at1.x + al0, 0.0f);
                const float h11 = fmaxf(cf[mt][nt][3] + at1.y + al1, 0.0f);
                sc[mt * 2 + 0][0] += h00 * wa0 + h01 * wb0;
                sc[mt * 2 + 0][1] += h00 * wa1 + h01 * wb1;
                sc[mt * 2 + 0][2] += h00 * wa2 + h01 * wb2;
                sc[mt * 2 + 1][0] += h10 * wa0 + h11 * wb0;
                sc[mt * 2 + 1][1] += h10 * wa1 + h11 * wb1;
                sc[mt * 2 + 1][2] += h10 * wa2 + h11 * wb2;
            }
        }
    }

    // ---- reduce over qc lanes, then across the 2 n-warps via shared ----
#pragma unroll
    for (int i = 0; i < 4; i++)
#pragma unroll
        for (int k = 0; k < 3; k++) {
            float v = sc[i][k];
            v += __shfl_xor_sync(0xffffffffu, v, 1);
            v += __shfl_xor_sync(0xffffffffu, v, 2);
            sc[i][k] = v;
        }
    if (qc == 0) {
#pragma unroll
        for (int i = 0; i < 4; i++) {
            int rl = wm * 32 + (i >> 1) * 16 + (i & 1) * 8 + qr;
            atomicAdd(&scr[rl * 3 + 0], sc[i][0]);
            atomicAdd(&scr[rl * 3 + 1], sc[i][1]);
            atomicAdd(&scr[rl * 3 + 2], sc[i][2]);
        }
    }
    __syncthreads();
    if (tid < BM) {
        const int row = wbase + tid;
        float* o = &out[(size_t)row * (C_NUM * 3) + c * 3];
        o[0] = scr[tid * 3 + 0] + __ldg(&b2[0]);
        o[1] = scr[tid * 3 + 1] + __ldg(&b2[1]);
        o[2] = scr[tid * 3 + 2] + __ldg(&b2[2]);
    }
}

// ---------------- launch ---------------------------------------------------
extern "C" void kernel_launch(void* const* d_in, const int* in_sizes, int n_in,
                              void* d_out, int out_size) {
    const float* tok_embs   = (const float*)d_in[0];   // (2048, 768)
    const int*   wmask      = (const int*)  d_in[1];   // (2048,)
    const float* label_embs = (const float*)d_in[3];   // (64, 768)
    const float* W_tok      = (const float*)d_in[4];   // (768, 1536)
    const float* b_tok      = (const float*)d_in[5];   // (1536,)
    const float* W_lab      = (const float*)d_in[6];   // (768, 1536)
    const float* b_lab      = (const float*)d_in[7];   // (1536,)
    const float* W1         = (const float*)d_in[8];   // (2304, 768)
    const float* b1         = (const float*)d_in[9];   // (768,)
    const float* W2         = (const float*)d_in[10];  // (768, 3)
    const float* b2         = (const float*)d_in[11];  // (3,)
    float* out = (float*)d_out;                        // (1024, 64, 3)

    float *we, *t, *lbp, *At, *Al;
    cudaGetSymbolAddress((void**)&we,  g_we);
    cudaGetSymbolAddress((void**)&t,   g_t);
    cudaGetSymbolAddress((void**)&lbp, g_lb);
    cudaGetSymbolAddress((void**)&At,  g_At);
    cudaGetSymbolAddress((void**)&Al,  g_Al);

    // idempotent, deterministic — no static guards (harness rule)
    cudaFuncSetAttribute(k_main_mma, cudaFuncAttributeMaxDynamicSharedMemorySize, SMEM_SZ);

    // 1) scatter pooling (last token index wins per word)
    k_init_winner<<<(W_NUM + 255) / 256, 256>>>();
    k_scatter<<<(L_TOK + 255) / 256, 256>>>(wmask);
    k_build_we<<<W_NUM, 256>>>(tok_embs);

    // 2) t = we @ W_tok + b_tok          (1024 x 1536, K=768)
    k_gemm_bias<<<dim3(W_NUM / 64, TH_DIM / 64), 256>>>(
        we, H_DIM, W_tok, TH_DIM, b_tok, t, TH_DIM, H_DIM);

    // 3) lb = label_embs @ W_lab + b_lab (64 x 1536, K=768)
    k_gemm_bias<<<dim3(1, TH_DIM / 64), 256>>>(
        label_embs, H_DIM, W_lab, TH_DIM, b_lab, lbp, TH_DIM, H_DIM);

    // 4) At = t0 @ W1_t + b1             (1024 x 768)
    k_gemm_bias<<<dim3(W_NUM / 64, H_DIM / 64), 256>>>(
        t, TH_DIM, W1, H_DIM, b1, At, H_DIM, H_DIM);

    // 5) Al = lb0 @ W1_l                 (64 x 768)
    k_gemm_bias<<<dim3(1, H_DIM / 64), 256>>>(
        lbp, TH_DIM, W1 + (size_t)H_DIM * H_DIM, H_DIM, nullptr, Al, H_DIM, H_DIM);

    // 6) fused tf32 mma prod-GEMM + relu + W2 contraction -> scores
    k_main_mma<<<dim3(W_NUM / BM, C_NUM), 256, SMEM_SZ>>>(
        t, lbp, At, Al, W1 + (size_t)2 * H_DIM * H_DIM, W2, b2, out);

    (void)in_sizes; (void)n_in; (void)out_size;
}

// round 6
// speedup vs baseline: 3.2346x; 1.2518x over previous
#include <cuda_runtime.h>
#include <cuda_bf16.h>
#include <cstdint>

// Problem constants (fixed shapes for GLiNERLinkerPooler_14671608283278)
#define L_TOK 2048
#define H_DIM 768
#define W_NUM 1024
#define C_NUM 64
#define TH_DIM 1536   // 2*H
// W1 is (2304, 768): rows [0,768)=W1_t, [768,1536)=W1_l, [1536,2304)=W1_p

// ---------------- device scratch (no allocations allowed) ----------------
__device__ int   g_winner[W_NUM];
__device__ float g_we[W_NUM * H_DIM];            // 3 MB
__device__ float g_t [W_NUM * TH_DIM];           // 6.3 MB
__device__ float g_lb[C_NUM * TH_DIM];           // 0.4 MB
__device__ float g_At[W_NUM * H_DIM];            // 3 MB  (t0@W1_t + b1)
__device__ float g_Al[C_NUM * H_DIM];            // 0.2 MB
__device__ float g_W1pr[H_DIM * H_DIM];          // 2.3 MB (tf32-rounded W1p)

// ---------------- helpers -------------------------------------------------
__device__ __forceinline__ float to_tf32(float x) {
    float r;
    asm("cvt.rna.tf32.f32 %0, %1;" : "=f"(r) : "f"(x));
    return r;
}
// m16n8k8 tf32 MMA (sm_80+ baseline PTX — no 'a'-arch features)
__device__ __forceinline__ void mma_tf32(float* c, const uint32_t* a,
                                         uint32_t b0, uint32_t b1) {
    asm volatile(
        "mma.sync.aligned.m16n8k8.row.col.f32.tf32.tf32.f32 "
        "{%0,%1,%2,%3}, {%4,%5,%6,%7}, {%8,%9}, {%0,%1,%2,%3};"
        : "+f"(c[0]), "+f"(c[1]), "+f"(c[2]), "+f"(c[3])
        : "r"(a[0]), "r"(a[1]), "r"(a[2]), "r"(a[3]), "r"(b0), "r"(b1));
}
__device__ __forceinline__ uint32_t smem_u32(const void* p) {
    uint32_t a;
    asm("{ .reg .u64 t; cvta.to.shared.u64 t, %1; cvt.u32.u64 %0, t; }" : "=r"(a) : "l"(p));
    return a;
}
__device__ __forceinline__ void cpasync16(uint32_t dst, const void* src) {
    asm volatile("cp.async.cg.shared.global [%0], [%1], 16;" :: "r"(dst), "l"(src));
}
#define CP_COMMIT()  asm volatile("cp.async.commit_group;" ::: "memory")
#define CP_WAIT2()   asm volatile("cp.async.wait_group 2;" ::: "memory")

// ---------------- step 1: winner per word (last token index wins) --------
__global__ void k_init_winner() {
    int w = blockIdx.x * blockDim.x + threadIdx.x;
    if (w < W_NUM) g_winner[w] = -1;
}
__global__ void k_scatter(const int* __restrict__ wmask) {
    int l = blockIdx.x * blockDim.x + threadIdx.x;
    if (l < L_TOK) {
        int v = wmask[l];
        if (v > 0 && v - 1 < W_NUM) atomicMax(&g_winner[v - 1], l);
    }
}
__global__ void k_build_we(const float* __restrict__ tok_embs) {
    int w = blockIdx.x;
    int src = g_winner[w];
    float* dst = &g_we[w * H_DIM];
    if (src >= 0) {
        const float* s = &tok_embs[src * H_DIM];
        for (int h = threadIdx.x; h < H_DIM; h += blockDim.x) dst[h] = s[h];
    } else {
        for (int h = threadIdx.x; h < H_DIM; h += blockDim.x) dst[h] = 0.0f;
    }
}

// ---------------- pre-round W1p to tf32 ----------------------------------
__global__ void k_round_w1p(const float* __restrict__ W1) {
    int i = blockIdx.x * blockDim.x + threadIdx.x;   // over float4s
    const float4* s = reinterpret_cast<const float4*>(W1 + (size_t)2 * H_DIM * H_DIM);
    float4* d = reinterpret_cast<float4*>(g_W1pr);
    if (i < H_DIM * H_DIM / 4) {
        float4 v = s[i];
        v.x = to_tf32(v.x); v.y = to_tf32(v.y);
        v.z = to_tf32(v.z); v.w = to_tf32(v.w);
        d[i] = v;
    }
}

// ---------------- generic tiled fp32 GEMM: C = A@B (+bias) ---------------
__global__ void k_gemm_bias(const float* __restrict__ A, int lda,
                            const float* __restrict__ B, int ldb,
                            const float* __restrict__ bias,
                            float* __restrict__ C, int ldc, int K) {
    __shared__ float As[16][64];
    __shared__ float Bs[16][64];
    const int tid = threadIdx.x;
    const int tx = tid & 15;
    const int ty = tid >> 4;
    const int mbase = blockIdx.x * 64;
    const int nbase = blockIdx.y * 64;

    float acc[4][4] = {};
    const int lw = tid >> 2, lkq = tid & 3;
    const int lkk = tid >> 4, lj4 = tid & 15;

    for (int k0 = 0; k0 < K; k0 += 16) {
        float4 va = *reinterpret_cast<const float4*>(&A[(size_t)(mbase + lw) * lda + k0 + lkq * 4]);
        As[lkq * 4 + 0][lw] = va.x;
        As[lkq * 4 + 1][lw] = va.y;
        As[lkq * 4 + 2][lw] = va.z;
        As[lkq * 4 + 3][lw] = va.w;
        *reinterpret_cast<float4*>(&Bs[lkk][lj4 * 4]) =
            *reinterpret_cast<const float4*>(&B[(size_t)(k0 + lkk) * ldb + nbase + lj4 * 4]);
        __syncthreads();
#pragma unroll
        for (int kk = 0; kk < 16; kk++) {
            float4 a4 = *reinterpret_cast<const float4*>(&As[kk][ty * 4]);
            float4 b4 = *reinterpret_cast<const float4*>(&Bs[kk][tx * 4]);
            float a[4] = {a4.x, a4.y, a4.z, a4.w};
            float b[4] = {b4.x, b4.y, b4.z, b4.w};
#pragma unroll
            for (int i = 0; i < 4; i++)
#pragma unroll
                for (int j = 0; j < 4; j++)
                    acc[i][j] = fmaf(a[i], b[j], acc[i][j]);
        }
        __syncthreads();
    }
#pragma unroll
    for (int j = 0; j < 4; j++) {
        int col = nbase + tx * 4 + j;
        float bv = bias ? bias[col] : 0.0f;
#pragma unroll
        for (int i = 0; i < 4; i++) {
            int row = mbase + ty * 4 + i;
            C[(size_t)row * ldc + col] = acc[i][j] + bv;
        }
    }
}

// ================== main fused mma.sync tf32 kernel =======================
// Grid (8, 64). Block 256 threads (8 warps, 4m x 2n). BM=128, BN=128,
// BK=16, 4-stage cp.async pipeline. A = raw t1 rows (scale lb1[c] applied
// in registers, rna-rounded); B = pre-rounded W1p. Fused epilogue:
// relu(P + At + Al) -> W2 contraction -> shfl + shared reduce -> scores.
#define BM 128
#define BN 128
#define BK 16
#define NJT 6                // 768 / BN
#define KTILES 48            // 768 / BK
#define NSTAGE 4
#define LDA 20               // BK + 4 pad (conflict-free frag LDS, 16B-aligned rows)
#define LDB 136              // BN + 8 pad (conflict-free frag LDS, 16B-aligned rows)
#define A_STAGE (BM * LDA)   // 2560 floats
#define B_STAGE (BK * LDB)   // 2176 floats

#define F_AS   0                          // 4*2560 = 10240
#define F_BS   10240                      // 4*2176 = 8704
#define F_LBS  18944                      // 768
#define F_ALS  19712                      // 768
#define F_W2S  20480                      // 2304
#define F_SCR  22784                      // 384
#define SMEM_FLOATS 23168
#define SMEM_SZ (SMEM_FLOATS * 4)         // 92672 bytes -> 2 blocks/SM

__global__ void __launch_bounds__(256, 2)
k_main_mma(const float* __restrict__ t,
           const float* __restrict__ lb,
           const float* __restrict__ At,    // (1024, 768)
           const float* __restrict__ Al,    // (64, 768)
           const float* __restrict__ W1pr,  // (768 h, 768 j) tf32-rounded
           const float* __restrict__ W2,    // (768, 3)
           const float* __restrict__ b2,
           float* __restrict__ out) {       // (1024, 64, 3)
    extern __shared__ float sm[];
    float* As  = sm + F_AS;
    float* Bs  = sm + F_BS;
    float* lbs = sm + F_LBS;
    float* als = sm + F_ALS;
    float* w2s = sm + F_W2S;
    float* scr = sm + F_SCR;
    const uint32_t sbA = smem_u32(As);
    const uint32_t sbB = smem_u32(Bs);

    const int tid = threadIdx.x;
    const int lane = tid & 31, wid = tid >> 5;
    const int wm = wid & 3, wn = wid >> 2;
    const int qr = lane >> 2, qc = lane & 3;
    const int c = blockIdx.y;
    const int wbase = blockIdx.x * BM;

    for (int i = tid; i < H_DIM; i += 256) {
        lbs[i] = lb[c * TH_DIM + H_DIM + i];
        als[i] = Al[c * H_DIM + i];
    }
    for (int i = tid; i < 3 * H_DIM; i += 256) w2s[i] = W2[i];
    for (int i = tid; i < BM * 3; i += 256) scr[i] = 0.0f;
    __syncthreads();

    // cp.async loader mapping (2 x 16B chunks per thread per tile per matrix)
    const int a_row = tid >> 2, a_c4 = tid & 3;     // A: 128 rows x 4 chunks
    const int b_kr  = tid >> 5, b_c4 = tid & 31;    // B: 16 rows x 32 chunks

    float sc[4][3];
#pragma unroll
    for (int i = 0; i < 4; i++)
#pragma unroll
        for (int k = 0; k < 3; k++) sc[i][k] = 0.0f;

    for (int jt = 0; jt < NJT; jt++) {
        const int jb = jt * BN;
        float cf[2][8][4];
#pragma unroll
        for (int mt = 0; mt < 2; mt++)
#pragma unroll
            for (int nt = 0; nt < 8; nt++)
#pragma unroll
                for (int r = 0; r < 4; r++) cf[mt][nt][r] = 0.0f;

        // ---- pipeline prologue: issue k-tiles 0..2 into stages 0..2 ----
#pragma unroll
        for (int p = 0; p < NSTAGE - 1; p++) {
            const int k0 = p * BK;
#pragma unroll
            for (int i = 0; i < 2; i++) {
                int idx = tid + 256 * i;
                int row = idx >> 2, c4 = idx & 3;
                cpasync16(sbA + (uint32_t)(p * A_STAGE + row * LDA + c4 * 4) * 4,
                          &t[(size_t)(wbase + row) * TH_DIM + H_DIM + k0 + c4 * 4]);
            }
#pragma unroll
            for (int i = 0; i < 2; i++) {
                int idx = tid + 256 * i;
                int kr = idx >> 5, cc = idx & 31;
                cpasync16(sbB + (uint32_t)(p * B_STAGE + kr * LDB + cc * 4) * 4,
                          &W1pr[(size_t)(k0 + kr) * H_DIM + jb + cc * 4]);
            }
            CP_COMMIT();
        }

        for (int kt = 0; kt < KTILES; kt++) {
            CP_WAIT2();
            __syncthreads();
            const int bi = kt & 3;
            const float* Asb = As + bi * A_STAGE;
            const float* Bsb = Bs + bi * B_STAGE;
            const int kbase = kt * BK;
#pragma unroll
            for (int k8 = 0; k8 < BK; k8 += 8) {
                const float s0 = lbs[kbase + k8 + qc];
                const float s1 = lbs[kbase + k8 + qc + 4];
                uint32_t a[2][4];
#pragma unroll
                for (int mt = 0; mt < 2; mt++) {
                    int rb = wm * 32 + mt * 16 + qr;
                    a[mt][0] = __float_as_uint(to_tf32(Asb[rb * LDA + k8 + qc] * s0));
                    a[mt][1] = __float_as_uint(to_tf32(Asb[(rb + 8) * LDA + k8 + qc] * s0));
                    a[mt][2] = __float_as_uint(to_tf32(Asb[rb * LDA + k8 + qc + 4] * s1));
                    a[mt][3] = __float_as_uint(to_tf32(Asb[(rb + 8) * LDA + k8 + qc + 4] * s1));
                }
#pragma unroll
                for (int nt = 0; nt < 8; nt++) {
                    int ncol = wn * 64 + nt * 8 + qr;
                    uint32_t b0 = __float_as_uint(Bsb[(k8 + qc) * LDB + ncol]);
                    uint32_t b1 = __float_as_uint(Bsb[(k8 + qc + 4) * LDB + ncol]);
                    mma_tf32(cf[0][nt], a[0], b0, b1);
                    mma_tf32(cf[1][nt], a[1], b0, b1);
                }
            }
            // ---- issue k-tile kt+3 into stage (kt+3)%4; always commit ----
            const int kn = kt + NSTAGE - 1;
            if (kn < KTILES) {
                const int st = kn & 3;
                const int k0 = kn * BK;
#pragma unroll
                for (int i = 0; i < 2; i++) {
                    int idx = tid + 256 * i;
                    int row = idx >> 2, c4 = idx & 3;
                    cpasync16(sbA + (uint32_t)(st * A_STAGE + row * LDA + c4 * 4) * 4,
                              &t[(size_t)(wbase + row) * TH_DIM + H_DIM + k0 + c4 * 4]);
                }
#pragma unroll
                for (int i = 0; i < 2; i++) {
                    int idx = tid + 256 * i;
                    int kr = idx >> 5, cc = idx & 31;
                    cpasync16(sbB + (uint32_t)(st * B_STAGE + kr * LDB + cc * 4) * 4,
                              &W1pr[(size_t)(k0 + kr) * H_DIM + jb + cc * 4]);
                }
            }
            CP_COMMIT();
        }

        // ---- fused epilogue for this j-tile ----
#pragma unroll
        for (int mt = 0; mt < 2; mt++) {
#pragma unroll
            for (int nt = 0; nt < 8; nt++) {
                const int gcol = jb + wn * 64 + nt * 8 + 2 * qc;
                const int row0 = wbase + wm * 32 + mt * 16 + qr;
                float2 at0 = __ldg(reinterpret_cast<const float2*>(&At[row0 * H_DIM + gcol]));
                float2 at1 = __ldg(reinterpret_cast<const float2*>(&At[(row0 + 8) * H_DIM + gcol]));
                const float al0 = als[gcol], al1 = als[gcol + 1];
                const float wa0 = w2s[gcol * 3 + 0], wa1 = w2s[gcol * 3 + 1], wa2 = w2s[gcol * 3 + 2];
                const float wb0 = w2s[gcol * 3 + 3], wb1 = w2s[gcol * 3 + 4], wb2 = w2s[gcol * 3 + 5];
                const float h00 = fmaxf(cf[mt][nt][0] + at0.x + al0, 0.0f);
                const float h01 = fmaxf(cf[mt][nt][1] + at0.y + al1, 0.0f);
                const float h10 = fmaxf(cf[mt][nt][2] + at1.x + al0, 0.0f);
                const float h11 = fmaxf(cf[mt][nt][3] + at1.y + al1, 0.0f);
                sc[mt * 2 + 0][0] += h00 * wa0 + h01 * wb0;
                sc[mt * 2 + 0][1] += h00 * wa1 + h01 * wb1;
                sc[mt * 2 + 0][2] += h00 * wa2 + h01 * wb2;
                sc[mt * 2 + 1][0] += h10 * wa0 + h11 * wb0;
                sc[mt * 2 + 1][1] += h10 * wa1 + h11 * wb1;
                sc[mt * 2 + 1][2] += h10 * wa2 + h11 * wb2;
            }
        }
    }

    // ---- reduce over qc lanes, then across the 2 n-warps via shared ----
#pragma unroll
    for (int i = 0; i < 4; i++)
#pragma unroll
        for (int k = 0; k < 3; k++) {
            float v = sc[i][k];
            v += __shfl_xor_sync(0xffffffffu, v, 1);
            v += __shfl_xor_sync(0xffffffffu, v, 2);
            sc[i][k] = v;
        }
    if (qc == 0) {
#pragma unroll
        for (int i = 0; i < 4; i++) {
            int rl = wm * 32 + (i >> 1) * 16 + (i & 1) * 8 + qr;
            atomicAdd(&scr[rl * 3 + 0], sc[i][0]);
            atomicAdd(&scr[rl * 3 + 1], sc[i][1]);
            atomicAdd(&scr[rl * 3 + 2], sc[i][2]);
        }
    }
    __syncthreads();
    if (tid < BM) {
        const int row = wbase + tid;
        float* o = &out[(size_t)row * (C_NUM * 3) + c * 3];
        o[0] = scr[tid * 3 + 0] + __ldg(&b2[0]);
        o[1] = scr[tid * 3 + 1] + __ldg(&b2[1]);
        o[2] = scr[tid * 3 + 2] + __ldg(&b2[2]);
    }
}

// ---------------- launch ---------------------------------------------------
extern "C" void kernel_launch(void* const* d_in, const int* in_sizes, int n_in,
                              void* d_out, int out_size) {
    const float* tok_embs   = (const float*)d_in[0];   // (2048, 768)
    const int*   wmask      = (const int*)  d_in[1];   // (2048,)
    const float* label_embs = (const float*)d_in[3];   // (64, 768)
    const float* W_tok      = (const float*)d_in[4];   // (768, 1536)
    const float* b_tok      = (const float*)d_in[5];   // (1536,)
    const float* W_lab      = (const float*)d_in[6];   // (768, 1536)
    const float* b_lab      = (const float*)d_in[7];   // (1536,)
    const float* W1         = (const float*)d_in[8];   // (2304, 768)
    const float* b1         = (const float*)d_in[9];   // (768,)
    const float* W2         = (const float*)d_in[10];  // (768, 3)
    const float* b2         = (const float*)d_in[11];  // (3,)
    float* out = (float*)d_out;                        // (1024, 64, 3)

    float *we, *t, *lbp, *At, *Al, *W1pr;
    cudaGetSymbolAddress((void**)&we,   g_we);
    cudaGetSymbolAddress((void**)&t,    g_t);
    cudaGetSymbolAddress((void**)&lbp,  g_lb);
    cudaGetSymbolAddress((void**)&At,   g_At);
    cudaGetSymbolAddress((void**)&Al,   g_Al);
    cudaGetSymbolAddress((void**)&W1pr, g_W1pr);

    // idempotent, deterministic — no static guards (harness rule)
    cudaFuncSetAttribute(k_main_mma, cudaFuncAttributeMaxDynamicSharedMemorySize, SMEM_SZ);

    // 0) pre-round W1p to tf32
    k_round_w1p<<<(H_DIM * H_DIM / 4 + 255) / 256, 256>>>(W1);

    // 1) scatter pooling (last token index wins per word)
    k_init_winner<<<(W_NUM + 255) / 256, 256>>>();
    k_scatter<<<(L_TOK + 255) / 256, 256>>>(wmask);
    k_build_we<<<W_NUM, 256>>>(tok_embs);

    // 2) t = we @ W_tok + b_tok          (1024 x 1536, K=768)
    k_gemm_bias<<<dim3(W_NUM / 64, TH_DIM / 64), 256>>>(
        we, H_DIM, W_tok, TH_DIM, b_tok, t, TH_DIM, H_DIM);

    // 3) lb = label_embs @ W_lab + b_lab (64 x 1536, K=768)
    k_gemm_bias<<<dim3(1, TH_DIM / 64), 256>>>(
        label_embs, H_DIM, W_lab, TH_DIM, b_lab, lbp, TH_DIM, H_DIM);

    // 4) At = t0 @ W1_t + b1             (1024 x 768)
    k_gemm_bias<<<dim3(W_NUM / 64, H_DIM / 64), 256>>>(
        t, TH_DIM, W1, H_DIM, b1, At, H_DIM, H_DIM);

    // 5) Al = lb0 @ W1_l                 (64 x 768)
    k_gemm_bias<<<dim3(1, H_DIM / 64), 256>>>(
        lbp, TH_DIM, W1 + (size_t)H_DIM * H_DIM, H_DIM, nullptr, Al, H_DIM, H_DIM);

    // 6) fused tf32 mma prod-GEMM + relu + W2 contraction -> scores
    k_main_mma<<<dim3(W_NUM / BM, C_NUM), 256, SMEM_SZ>>>(
        t, lbp, At, Al, W1pr, W2, b2, out);

    (void)in_sizes; (void)n_in; (void)out_size;
}

// round 7
// speedup vs baseline: 3.7389x; 1.1559x over previous
#include <cuda_runtime.h>
#include <cuda_fp16.h>
#include <cstdint>

// Problem constants (fixed shapes for GLiNERLinkerPooler_14671608283278)
#define L_TOK 2048
#define H_DIM 768
#define W_NUM 1024
#define C_NUM 64
#define TH_DIM 1536   // 2*H
// W1 is (2304, 768): rows [0,768)=W1_t, [768,1536)=W1_l, [1536,2304)=W1_p

// ---------------- device scratch (no allocations allowed) ----------------
__device__ int    g_winner[W_NUM];
__device__ float  g_we[W_NUM * H_DIM];            // 3 MB
__device__ float  g_t [W_NUM * TH_DIM];           // 6.3 MB
__device__ float  g_lb[C_NUM * TH_DIM];           // 0.4 MB
__device__ float  g_At[W_NUM * H_DIM];            // 3 MB  (t0@W1_t + b1)
__device__ float  g_Al[C_NUM * H_DIM];            // 0.2 MB
__device__ float  g_W1pT[H_DIM * H_DIM];          // 2.3 MB (W1p transposed: [j][h])
__device__ __half g_t1h[W_NUM * H_DIM];           // 1.5 MB (half(t1))
__device__ __half g_Bc[(size_t)C_NUM * H_DIM * H_DIM]; // 75.5 MB: half(lb1[c,k]*W1p[k,j]) as [c][j][k]

// ---------------- helpers -------------------------------------------------
// m16n8k16 fp16 MMA, f32 accumulate (sm_80+ baseline PTX)
__device__ __forceinline__ void mma_f16(float* c, const uint32_t* a,
                                        uint32_t b0, uint32_t b1) {
    asm volatile(
        "mma.sync.aligned.m16n8k16.row.col.f32.f16.f16.f32 "
        "{%0,%1,%2,%3}, {%4,%5,%6,%7}, {%8,%9}, {%0,%1,%2,%3};"
        : "+f"(c[0]), "+f"(c[1]), "+f"(c[2]), "+f"(c[3])
        : "r"(a[0]), "r"(a[1]), "r"(a[2]), "r"(a[3]), "r"(b0), "r"(b1));
}
__device__ __forceinline__ uint32_t smem_u32(const void* p) {
    uint32_t a;
    asm("{ .reg .u64 t; cvta.to.shared.u64 t, %1; cvt.u32.u64 %0, t; }" : "=r"(a) : "l"(p));
    return a;
}
__device__ __forceinline__ void cpasync16(uint32_t dst, const void* src) {
    asm volatile("cp.async.cg.shared.global [%0], [%1], 16;" :: "r"(dst), "l"(src));
}
#define CP_COMMIT()  asm volatile("cp.async.commit_group;" ::: "memory")
#define CP_WAIT2()   asm volatile("cp.async.wait_group 2;" ::: "memory")

// ---------------- step 1: winner per word (last token index wins) --------
__global__ void k_init_winner() {
    int w = blockIdx.x * blockDim.x + threadIdx.x;
    if (w < W_NUM) g_winner[w] = -1;
}
__global__ void k_scatter(const int* __restrict__ wmask) {
    int l = blockIdx.x * blockDim.x + threadIdx.x;
    if (l < L_TOK) {
        int v = wmask[l];
        if (v > 0 && v - 1 < W_NUM) atomicMax(&g_winner[v - 1], l);
    }
}
__global__ void k_build_we(const float* __restrict__ tok_embs) {
    int w = blockIdx.x;
    int src = g_winner[w];
    float* dst = &g_we[w * H_DIM];
    if (src >= 0) {
        const float* s = &tok_embs[src * H_DIM];
        for (int h = threadIdx.x; h < H_DIM; h += blockDim.x) dst[h] = s[h];
    } else {
        for (int h = threadIdx.x; h < H_DIM; h += blockDim.x) dst[h] = 0.0f;
    }
}

// ---------------- W1p transpose: (h,j) -> (j,h) ---------------------------
__global__ void k_transpose768(const float* __restrict__ src, float* __restrict__ dst) {
    __shared__ float tl[32][33];
    int j0 = blockIdx.x * 32, h0 = blockIdx.y * 32;
    for (int dy = threadIdx.y; dy < 32; dy += 8)
        tl[dy][threadIdx.x] = src[(size_t)(h0 + dy) * H_DIM + j0 + threadIdx.x];
    __syncthreads();
    for (int dy = threadIdx.y; dy < 32; dy += 8)
        dst[(size_t)(j0 + dy) * H_DIM + h0 + threadIdx.x] = tl[threadIdx.x][dy];
}

// ---------------- t1 -> half ----------------------------------------------
__global__ void k_t1_half() {
    int i = blockIdx.x * blockDim.x + threadIdx.x;   // over half2 slots
    if (i < W_NUM * H_DIM / 2) {
        int w = i / (H_DIM / 2), kk = i % (H_DIM / 2);
        float2 v = *reinterpret_cast<const float2*>(&g_t[(size_t)w * TH_DIM + H_DIM + kk * 2]);
        reinterpret_cast<__half2*>(g_t1h)[i] = __floats2half2_rn(v.x, v.y);
    }
}

// ---------------- Bc[c][j][k] = half(lb1[c,k] * W1pT[j,k]) ----------------
// grid (96 j-blocks of 8, 64 c), block 256
__global__ void k_make_bc() {
    const int c = blockIdx.y;
    const int j0 = blockIdx.x * 8;
    const float* lb1 = &g_lb[(size_t)c * TH_DIM + H_DIM];
    __half2* out = reinterpret_cast<__half2*>(
        &g_Bc[((size_t)c * H_DIM + j0) * H_DIM]);
#pragma unroll
    for (int i = 0; i < 12; i++) {                  // 8*384 half2 slots / 256
        int slot = threadIdx.x + 256 * i;
        int jj = slot / (H_DIM / 2), kk = slot % (H_DIM / 2);
        float2 w = *reinterpret_cast<const float2*>(&g_W1pT[(size_t)(j0 + jj) * H_DIM + kk * 2]);
        float2 s = *reinterpret_cast<const float2*>(&lb1[kk * 2]);
        out[slot] = __floats2half2_rn(w.x * s.x, w.y * s.y);
    }
}

// ---------------- generic tiled fp32 GEMM: C = A@B (+bias) ---------------
__global__ void k_gemm_bias(const float* __restrict__ A, int lda,
                            const float* __restrict__ B, int ldb,
                            const float* __restrict__ bias,
                            float* __restrict__ C, int ldc, int K) {
    __shared__ float As[16][64];
    __shared__ float Bs[16][64];
    const int tid = threadIdx.x;
    const int tx = tid & 15;
    const int ty = tid >> 4;
    const int mbase = blockIdx.x * 64;
    const int nbase = blockIdx.y * 64;

    float acc[4][4] = {};
    const int lw = tid >> 2, lkq = tid & 3;
    const int lkk = tid >> 4, lj4 = tid & 15;

    for (int k0 = 0; k0 < K; k0 += 16) {
        float4 va = *reinterpret_cast<const float4*>(&A[(size_t)(mbase + lw) * lda + k0 + lkq * 4]);
        As[lkq * 4 + 0][lw] = va.x;
        As[lkq * 4 + 1][lw] = va.y;
        As[lkq * 4 + 2][lw] = va.z;
        As[lkq * 4 + 3][lw] = va.w;
        *reinterpret_cast<float4*>(&Bs[lkk][lj4 * 4]) =
            *reinterpret_cast<const float4*>(&B[(size_t)(k0 + lkk) * ldb + nbase + lj4 * 4]);
        __syncthreads();
#pragma unroll
        for (int kk = 0; kk < 16; kk++) {
            float4 a4 = *reinterpret_cast<const float4*>(&As[kk][ty * 4]);
            float4 b4 = *reinterpret_cast<const float4*>(&Bs[kk][tx * 4]);
            float a[4] = {a4.x, a4.y, a4.z, a4.w};
            float b[4] = {b4.x, b4.y, b4.z, b4.w};
#pragma unroll
            for (int i = 0; i < 4; i++)
#pragma unroll
                for (int j = 0; j < 4; j++)
                    acc[i][j] = fmaf(a[i], b[j], acc[i][j]);
        }
        __syncthreads();
    }
#pragma unroll
    for (int j = 0; j < 4; j++) {
        int col = nbase + tx * 4 + j;
        float bv = bias ? bias[col] : 0.0f;
#pragma unroll
        for (int i = 0; i < 4; i++) {
            int row = mbase + ty * 4 + i;
            C[(size_t)row * ldc + col] = acc[i][j] + bv;
        }
    }
}

// ================== main fused fp16 mma kernel ============================
// Grid (8, 64). Block 256 (8 warps, 4m x 2n). BM=128, BN=128, BK=16,
// 4-stage cp.async. A = t1h [m][k] half, B = Bc[c] [n][k] half (scale baked).
// Fused epilogue: relu(P + At + Al) -> W2 contraction -> reduce -> scores.
#define BM 128
#define BN 128
#define BK 16
#define NJT 6                 // 768 / BN
#define KTILES 48             // 768 / BK
#define NSTAGE 4
#define LDH 24                // halves per row (16 + 8 pad): 48B rows, bank = 12r+qc, conflict-free
#define A_STAGE_B (BM * LDH * 2)   // 6144 bytes
#define B_STAGE_B (BN * LDH * 2)   // 6144 bytes

#define O_AS   0
#define O_BS   (4 * A_STAGE_B)                // 24576
#define O_ALS  (O_BS + 4 * B_STAGE_B)         // 49152
#define O_W2S  (O_ALS + H_DIM * 4)            // 52224
#define O_SCR  (O_W2S + 3 * H_DIM * 4)        // 61440
#define SMEM_SZ (O_SCR + BM * 3 * 4)          // 62976 bytes

__global__ void __launch_bounds__(256, 2)
k_main_mma(const __half* __restrict__ t1h,    // (1024, 768)
           const __half* __restrict__ Bc,     // (64, 768 j, 768 k)
           const float* __restrict__ At,      // (1024, 768)
           const float* __restrict__ Al,      // (64, 768)
           const float* __restrict__ W2,      // (768, 3)
           const float* __restrict__ b2,
           float* __restrict__ out) {         // (1024, 64, 3)
    extern __shared__ char smc[];
    __half* Ash = reinterpret_cast<__half*>(smc + O_AS);
    __half* Bsh = reinterpret_cast<__half*>(smc + O_BS);
    float* als = reinterpret_cast<float*>(smc + O_ALS);
    float* w2s = reinterpret_cast<float*>(smc + O_W2S);
    float* scr = reinterpret_cast<float*>(smc + O_SCR);
    const uint32_t sbA = smem_u32(Ash);
    const uint32_t sbB = smem_u32(Bsh);

    const int tid = threadIdx.x;
    const int lane = tid & 31, wid = tid >> 5;
    const int wm = wid & 3, wn = wid >> 2;
    const int qr = lane >> 2, qc = lane & 3;
    const int c = blockIdx.y;
    const int wbase = blockIdx.x * BM;

    for (int i = tid; i < H_DIM; i += 256) als[i] = Al[c * H_DIM + i];
    for (int i = tid; i < 3 * H_DIM; i += 256) w2s[i] = W2[i];
    for (int i = tid; i < BM * 3; i += 256) scr[i] = 0.0f;
    __syncthreads();

    const __half* Bcc = Bc + (size_t)c * H_DIM * H_DIM;
    // loader mapping: 256 chunks of 16B per tile per matrix -> 1 chunk/thread
    const int l_row = tid >> 1, l_ch = tid & 1;   // row 0..127, 16B-chunk 0..1

    float sc[4][3];
#pragma unroll
    for (int i = 0; i < 4; i++)
#pragma unroll
        for (int k = 0; k < 3; k++) sc[i][k] = 0.0f;

    for (int jt = 0; jt < NJT; jt++) {
        const int jb = jt * BN;
        float cf[2][8][4];
#pragma unroll
        for (int mt = 0; mt < 2; mt++)
#pragma unroll
            for (int nt = 0; nt < 8; nt++)
#pragma unroll
                for (int r = 0; r < 4; r++) cf[mt][nt][r] = 0.0f;

        // ---- pipeline prologue: k-tiles 0..2 into stages 0..2 ----
#pragma unroll
        for (int p = 0; p < NSTAGE - 1; p++) {
            const int k0 = p * BK;
            cpasync16(sbA + (uint32_t)(p * A_STAGE_B + l_row * (LDH * 2) + l_ch * 16),
                      &t1h[(size_t)(wbase + l_row) * H_DIM + k0 + l_ch * 8]);
            cpasync16(sbB + (uint32_t)(p * B_STAGE_B + l_row * (LDH * 2) + l_ch * 16),
                      &Bcc[(size_t)(jb + l_row) * H_DIM + k0 + l_ch * 8]);
            CP_COMMIT();
        }

        for (int kt = 0; kt < KTILES; kt++) {
            CP_WAIT2();
            __syncthreads();
            const int bi = kt & 3;
            const __half* Asb = Ash + bi * (A_STAGE_B / 2);
            const __half* Bsb = Bsh + bi * (B_STAGE_B / 2);
            // fragments
            uint32_t a[2][4];
#pragma unroll
            for (int mt = 0; mt < 2; mt++) {
                int rb = wm * 32 + mt * 16 + qr;
                a[mt][0] = *reinterpret_cast<const uint32_t*>(&Asb[rb * LDH + 2 * qc]);
                a[mt][1] = *reinterpret_cast<const uint32_t*>(&Asb[(rb + 8) * LDH + 2 * qc]);
                a[mt][2] = *reinterpret_cast<const uint32_t*>(&Asb[rb * LDH + 2 * qc + 8]);
                a[mt][3] = *reinterpret_cast<const uint32_t*>(&Asb[(rb + 8) * LDH + 2 * qc + 8]);
            }
#pragma unroll
            for (int nt = 0; nt < 8; nt++) {
                int ncol = wn * 64 + nt * 8 + qr;
                uint32_t b0 = *reinterpret_cast<const uint32_t*>(&Bsb[ncol * LDH + 2 * qc]);
                uint32_t b1 = *reinterpret_cast<const uint32_t*>(&Bsb[ncol * LDH + 2 * qc + 8]);
                mma_f16(cf[0][nt], a[0], b0, b1);
                mma_f16(cf[1][nt], a[1], b0, b1);
            }
            // ---- issue k-tile kt+3; always commit to keep group count fixed ----
            const int kn = kt + NSTAGE - 1;
            if (kn < KTILES) {
                const int st = kn & 3;
                const int k0 = kn * BK;
                cpasync16(sbA + (uint32_t)(st * A_STAGE_B + l_row * (LDH * 2) + l_ch * 16),
                          &t1h[(size_t)(wbase + l_row) * H_DIM + k0 + l_ch * 8]);
                cpasync16(sbB + (uint32_t)(st * B_STAGE_B + l_row * (LDH * 2) + l_ch * 16),
                          &Bcc[(size_t)(jb + l_row) * H_DIM + k0 + l_ch * 8]);
            }
            CP_COMMIT();
        }

        // ---- fused epilogue for this j-tile ----
#pragma unroll
        for (int mt = 0; mt < 2; mt++) {
#pragma unroll
            for (int nt = 0; nt < 8; nt++) {
                const int gcol = jb + wn * 64 + nt * 8 + 2 * qc;
                const int row0 = wbase + wm * 32 + mt * 16 + qr;
                float2 at0 = __ldg(reinterpret_cast<const float2*>(&At[row0 * H_DIM + gcol]));
                float2 at1 = __ldg(reinterpret_cast<const float2*>(&At[(row0 + 8) * H_DIM + gcol]));
                const float al0 = als[gcol], al1 = als[gcol + 1];
                const float wa0 = w2s[gcol * 3 + 0], wa1 = w2s[gcol * 3 + 1], wa2 = w2s[gcol * 3 + 2];
                const float wb0 = w2s[gcol * 3 + 3], wb1 = w2s[gcol * 3 + 4], wb2 = w2s[gcol * 3 + 5];
                const float h00 = fmaxf(cf[mt][nt][0] + at0.x + al0, 0.0f);
                const float h01 = fmaxf(cf[mt][nt][1] + at0.y + al1, 0.0f);
                const float h10 = fmaxf(cf[mt][nt][2] + at1.x + al0, 0.0f);
                const float h11 = fmaxf(cf[mt][nt][3] + at1.y + al1, 0.0f);
                sc[mt * 2 + 0][0] += h00 * wa0 + h01 * wb0;
                sc[mt * 2 + 0][1] += h00 * wa1 + h01 * wb1;
                sc[mt * 2 + 0][2] += h00 * wa2 + h01 * wb2;
                sc[mt * 2 + 1][0] += h10 * wa0 + h11 * wb0;
                sc[mt * 2 + 1][1] += h10 * wa1 + h11 * wb1;
                sc[mt * 2 + 1][2] += h10 * wa2 + h11 * wb2;
            }
        }
    }

    // ---- reduce over qc lanes, then across n-warps via shared atomics ----
#pragma unroll
    for (int i = 0; i < 4; i++)
#pragma unroll
        for (int k = 0; k < 3; k++) {
            float v = sc[i][k];
            v += __shfl_xor_sync(0xffffffffu, v, 1);
            v += __shfl_xor_sync(0xffffffffu, v, 2);
            sc[i][k] = v;
        }
    if (qc == 0) {
#pragma unroll
        for (int i = 0; i < 4; i++) {
            int rl = wm * 32 + (i >> 1) * 16 + (i & 1) * 8 + qr;
            atomicAdd(&scr[rl * 3 + 0], sc[i][0]);
            atomicAdd(&scr[rl * 3 + 1], sc[i][1]);
            atomicAdd(&scr[rl * 3 + 2], sc[i][2]);
        }
    }
    __syncthreads();
    if (tid < BM) {
        const int row = wbase + tid;
        float* o = &out[(size_t)row * (C_NUM * 3) + c * 3];
        o[0] = scr[tid * 3 + 0] + __ldg(&b2[0]);
        o[1] = scr[tid * 3 + 1] + __ldg(&b2[1]);
        o[2] = scr[tid * 3 + 2] + __ldg(&b2[2]);
    }
}

// ---------------- launch ---------------------------------------------------
extern "C" void kernel_launch(void* const* d_in, const int* in_sizes, int n_in,
                              void* d_out, int out_size) {
    const float* tok_embs   = (const float*)d_in[0];   // (2048, 768)
    const int*   wmask      = (const int*)  d_in[1];   // (2048,)
    const float* label_embs = (const float*)d_in[3];   // (64, 768)
    const float* W_tok      = (const float*)d_in[4];   // (768, 1536)
    const float* b_tok      = (const float*)d_in[5];   // (1536,)
    const float* W_lab      = (const float*)d_in[6];   // (768, 1536)
    const float* b_lab      = (const float*)d_in[7];   // (1536,)
    const float* W1         = (const float*)d_in[8];   // (2304, 768)
    const float* b1         = (const float*)d_in[9];   // (768,)
    const float* W2         = (const float*)d_in[10];  // (768, 3)
    const float* b2         = (const float*)d_in[11];  // (3,)
    float* out = (float*)d_out;                        // (1024, 64, 3)

    float *we, *t, *lbp, *At, *Al, *W1pT;
    __half *t1h, *Bc;
    cudaGetSymbolAddress((void**)&we,   g_we);
    cudaGetSymbolAddress((void**)&t,    g_t);
    cudaGetSymbolAddress((void**)&lbp,  g_lb);
    cudaGetSymbolAddress((void**)&At,   g_At);
    cudaGetSymbolAddress((void**)&Al,   g_Al);
    cudaGetSymbolAddress((void**)&W1pT, g_W1pT);
    cudaGetSymbolAddress((void**)&t1h,  g_t1h);
    cudaGetSymbolAddress((void**)&Bc,   g_Bc);

    // idempotent, deterministic — no static guards (harness rule)
    cudaFuncSetAttribute(k_main_mma, cudaFuncAttributeMaxDynamicSharedMemorySize, SMEM_SZ);

    // 0) transpose W1p -> (j, h)  (independent of data kernels)
    k_transpose768<<<dim3(H_DIM / 32, H_DIM / 32), dim3(32, 8)>>>(
        W1 + (size_t)2 * H_DIM * H_DIM, W1pT);

    // 1) scatter pooling (last token index wins per word)
    k_init_winner<<<(W_NUM + 255) / 256, 256>>>();
    k_scatter<<<(L_TOK + 255) / 256, 256>>>(wmask);
    k_build_we<<<W_NUM, 256>>>(tok_embs);

    // 2) t = we @ W_tok + b_tok          (1024 x 1536, K=768)
    k_gemm_bias<<<dim3(W_NUM / 64, TH_DIM / 64), 256>>>(
        we, H_DIM, W_tok, TH_DIM, b_tok, t, TH_DIM, H_DIM);

    // 3) lb = label_embs @ W_lab + b_lab (64 x 1536, K=768)
    k_gemm_bias<<<dim3(1, TH_DIM / 64), 256>>>(
        label_embs, H_DIM, W_lab, TH_DIM, b_lab, lbp, TH_DIM, H_DIM);

    // 4) half conversions: t1h = half(t1);  Bc[c][j][k] = half(lb1[c,k]*W1pT[j,k])
    k_t1_half<<<(W_NUM * H_DIM / 2 + 255) / 256, 256>>>();
    k_make_bc<<<dim3(H_DIM / 8, C_NUM), 256>>>();

    // 5) At = t0 @ W1_t + b1             (1024 x 768)
    k_gemm_bias<<<dim3(W_NUM / 64, H_DIM / 64), 256>>>(
        t, TH_DIM, W1, H_DIM, b1, At, H_DIM, H_DIM);

    // 6) Al = lb0 @ W1_l                 (64 x 768)
    k_gemm_bias<<<dim3(1, H_DIM / 64), 256>>>(
        lbp, TH_DIM, W1 + (size_t)H_DIM * H_DIM, H_DIM, nullptr, Al, H_DIM, H_DIM);

    // 7) fused fp16 mma prod-GEMM + relu + W2 contraction -> scores
    k_main_mma<<<dim3(W_NUM / BM, C_NUM), 256, SMEM_SZ>>>(
        t1h, Bc, At, Al, W2, b2, out);

    (void)in_sizes; (void)n_in; (void)out_size;
}

// round 9
// speedup vs baseline: 4.9771x; 1.3312x over previous
#include <cuda_runtime.h>
#include <cuda_fp16.h>
#include <cstdint>

// Problem constants (fixed shapes for GLiNERLinkerPooler_14671608283278)
#define L_TOK 2048
#define H_DIM 768
#define W_NUM 1024
#define C_NUM 64
#define TH_DIM 1536   // 2*H
// W1 is (2304, 768): rows [0,768)=W1_t, [768,1536)=W1_l, [1536,2304)=W1_p

// ---------------- device scratch (no allocations allowed) ----------------
__device__ int    g_winner[W_NUM];
__device__ __half g_weh[W_NUM * H_DIM];           // 1.5 MB half(we)
__device__ __half g_WtokT[TH_DIM * H_DIM];        // 2.3 MB half(W_tok^T) [n][k]
__device__ __half g_W1tT[H_DIM * H_DIM];          // 1.1 MB half(W1_t^T)  [n][k]
__device__ __half g_t01h[W_NUM * TH_DIM];         // 3 MB   half(t) [w][2H]
__device__ float  g_lb[C_NUM * TH_DIM];           // 0.4 MB
__device__ float  g_At[W_NUM * H_DIM];            // 3 MB  (t0@W1_t + b1)
__device__ float  g_Al[C_NUM * H_DIM];            // 0.2 MB
__device__ float  g_W1pT[H_DIM * H_DIM];          // 2.3 MB (W1p^T fp32: [j][h])
__device__ __half g_Bc[(size_t)C_NUM * H_DIM * H_DIM]; // 75.5 MB half(lb1[c,k]*W1p[k,j]) [c][j][k]

// ---------------- helpers -------------------------------------------------
// m16n8k16 fp16 MMA, f32 accumulate (sm_80+ baseline PTX)
__device__ __forceinline__ void mma_f16(float* c, const uint32_t* a,
                                        uint32_t b0, uint32_t b1) {
    asm volatile(
        "mma.sync.aligned.m16n8k16.row.col.f32.f16.f16.f32 "
        "{%0,%1,%2,%3}, {%4,%5,%6,%7}, {%8,%9}, {%0,%1,%2,%3};"
        : "+f"(c[0]), "+f"(c[1]), "+f"(c[2]), "+f"(c[3])
        : "r"(a[0]), "r"(a[1]), "r"(a[2]), "r"(a[3]), "r"(b0), "r"(b1));
}
__device__ __forceinline__ uint32_t smem_u32(const void* p) {
    uint32_t a;
    asm("{ .reg .u64 t; cvta.to.shared.u64 t, %1; cvt.u32.u64 %0, t; }" : "=r"(a) : "l"(p));
    return a;
}
__device__ __forceinline__ void cpasync16(uint32_t dst, const void* src) {
    asm volatile("cp.async.cg.shared.global [%0], [%1], 16;" :: "r"(dst), "l"(src));
}
#define CP_COMMIT()  asm volatile("cp.async.commit_group;" ::: "memory")
#define CP_WAIT2()   asm volatile("cp.async.wait_group 2;" ::: "memory")

// ---------------- scatter pooling (last token index wins) ----------------
__global__ void k_init_winner() {
    int w = blockIdx.x * blockDim.x + threadIdx.x;
    if (w < W_NUM) g_winner[w] = -1;
}
__global__ void k_scatter(const int* __restrict__ wmask) {
    int l = blockIdx.x * blockDim.x + threadIdx.x;
    if (l < L_TOK) {
        int v = wmask[l];
        if (v > 0 && v - 1 < W_NUM) atomicMax(&g_winner[v - 1], l);
    }
}
__global__ void k_build_we_h(const float* __restrict__ tok_embs) {
    int w = blockIdx.x;
    int src = g_winner[w];
    __half* dst = &g_weh[w * H_DIM];
    if (src >= 0) {
        const float* s = &tok_embs[(size_t)src * H_DIM];
        for (int h = threadIdx.x; h < H_DIM; h += blockDim.x) dst[h] = __float2half(s[h]);
    } else {
        for (int h = threadIdx.x; h < H_DIM; h += blockDim.x) dst[h] = __float2half(0.0f);
    }
}

// ---------------- transposes ----------------------------------------------
// fp32 (h,j)->(j,h), 768x768
__global__ void k_transpose768(const float* __restrict__ src, float* __restrict__ dst) {
    __shared__ float tl[32][33];
    int j0 = blockIdx.x * 32, h0 = blockIdx.y * 32;
    for (int dy = threadIdx.y; dy < 32; dy += 8)
        tl[dy][threadIdx.x] = src[(size_t)(h0 + dy) * H_DIM + j0 + threadIdx.x];
    __syncthreads();
    for (int dy = threadIdx.y; dy < 32; dy += 8)
        dst[(size_t)(j0 + dy) * H_DIM + h0 + threadIdx.x] = tl[threadIdx.x][dy];
}
// fp32 src[K][N] -> half dst[N][K]
__global__ void k_transpose_h(const float* __restrict__ src, __half* __restrict__ dst,
                              int K, int N) {
    __shared__ float tl[32][33];
    int n0 = blockIdx.x * 32, k0 = blockIdx.y * 32;
    for (int dy = threadIdx.y; dy < 32; dy += 8)
        tl[dy][threadIdx.x] = src[(size_t)(k0 + dy) * N + n0 + threadIdx.x];
    __syncthreads();
    for (int dy = threadIdx.y; dy < 32; dy += 8)
        dst[(size_t)(n0 + dy) * K + k0 + threadIdx.x] = __float2half(tl[threadIdx.x][dy]);
}

// ---------------- Bc[c][j][k] = half(lb1[c,k] * W1pT[j,k]) ----------------
__global__ void k_make_bc() {
    const int c = blockIdx.y;
    const int j0 = blockIdx.x * 8;
    const float* lb1 = &g_lb[(size_t)c * TH_DIM + H_DIM];
    __half2* out = reinterpret_cast<__half2*>(&g_Bc[((size_t)c * H_DIM + j0) * H_DIM]);
#pragma unroll
    for (int i = 0; i < 12; i++) {
        int slot = threadIdx.x + 256 * i;
        int jj = slot / (H_DIM / 2), kk = slot % (H_DIM / 2);
        float2 w = *reinterpret_cast<const float2*>(&g_W1pT[(size_t)(j0 + jj) * H_DIM + kk * 2]);
        float2 s = *reinterpret_cast<const float2*>(&lb1[kk * 2]);
        out[slot] = __floats2half2_rn(w.x * s.x, w.y * s.y);
    }
}

// ---------------- SIMT fp32 GEMM (small label-side GEMMs only) ------------
__global__ void k_gemm_bias(const float* __restrict__ A, int lda,
                            const float* __restrict__ B, int ldb,
                            const float* __restrict__ bias,
                            float* __restrict__ C, int ldc, int K) {
    __shared__ float As[16][64];
    __shared__ float Bs[16][64];
    const int tid = threadIdx.x;
    const int tx = tid & 15;
    const int ty = tid >> 4;
    const int mbase = blockIdx.x * 64;
    const int nbase = blockIdx.y * 64;

    float acc[4][4] = {};
    const int lw = tid >> 2, lkq = tid & 3;
    const int lkk = tid >> 4, lj4 = tid & 15;

    for (int k0 = 0; k0 < K; k0 += 16) {
        float4 va = *reinterpret_cast<const float4*>(&A[(size_t)(mbase + lw) * lda + k0 + lkq * 4]);
        As[lkq * 4 + 0][lw] = va.x;
        As[lkq * 4 + 1][lw] = va.y;
        As[lkq * 4 + 2][lw] = va.z;
        As[lkq * 4 + 3][lw] = va.w;
        *reinterpret_cast<float4*>(&Bs[lkk][lj4 * 4]) =
            *reinterpret_cast<const float4*>(&B[(size_t)(k0 + lkk) * ldb + nbase + lj4 * 4]);
        __syncthreads();
#pragma unroll
        for (int kk = 0; kk < 16; kk++) {
            float4 a4 = *reinterpret_cast<const float4*>(&As[kk][ty * 4]);
            float4 b4 = *reinterpret_cast<const float4*>(&Bs[kk][tx * 4]);
            float a[4] = {a4.x, a4.y, a4.z, a4.w};
            float b[4] = {b4.x, b4.y, b4.z, b4.w};
#pragma unroll
            for (int i = 0; i < 4; i++)
#pragma unroll
                for (int j = 0; j < 4; j++)
                    acc[i][j] = fmaf(a[i], b[j], acc[i][j]);
        }
        __syncthreads();
    }
#pragma unroll
    for (int j = 0; j < 4; j++) {
        int col = nbase + tx * 4 + j;
        float bv = bias ? bias[col] : 0.0f;
#pragma unroll
        for (int i = 0; i < 4; i++) {
            int row = mbase + ty * 4 + i;
            C[(size_t)row * ldc + col] = acc[i][j] + bv;
        }
    }
}

// ================== generic fp16 mma GEMM (prologue) ======================
// C[M,N] = A[M,K]h @ B[N,K]h^T + bias. BM=BN=128, BK=16, 4-stage cp.async.
// K fixed at 768. OUT_HALF: write half C, else float C.
// Dynamic shared: A 4 stages then B 4 stages (6144 B each half).
#define PLDH 24
#define PKT  48
#define PA_STAGE_B (128 * PLDH * 2)   // 6144 bytes
#define PSMEM_SZ (8 * PA_STAGE_B)     // 49152 bytes

template <bool OUT_HALF>
__global__ void __launch_bounds__(256)
k_gemm_h(const __half* __restrict__ A, int lda,
         const __half* __restrict__ B, int ldb,
         const float* __restrict__ bias,
         void* __restrict__ Cv, int ldc) {
    extern __shared__ char psm[];
    __half* Ash = reinterpret_cast<__half*>(psm);
    __half* Bsh = reinterpret_cast<__half*>(psm + 4 * PA_STAGE_B);
    const uint32_t sbA = smem_u32(Ash);
    const uint32_t sbB = smem_u32(Bsh);

    const int tid = threadIdx.x;
    const int lane = tid & 31, wid = tid >> 5;
    const int wm = wid & 3, wn = wid >> 2;
    const int qr = lane >> 2, qc = lane & 3;
    const int mb = blockIdx.x * 128;
    const int nb = blockIdx.y * 128;
    const int l_row = tid >> 1, l_ch = tid & 1;

    float cf[2][8][4];
#pragma unroll
    for (int mt = 0; mt < 2; mt++)
#pragma unroll
        for (int nt = 0; nt < 8; nt++)
#pragma unroll
            for (int r = 0; r < 4; r++) cf[mt][nt][r] = 0.0f;

#pragma unroll
    for (int p = 0; p < 3; p++) {
        const int k0 = p * 16;
        cpasync16(sbA + (uint32_t)(p * PA_STAGE_B + l_row * (PLDH * 2) + l_ch * 16),
                  &A[(size_t)(mb + l_row) * lda + k0 + l_ch * 8]);
        cpasync16(sbB + (uint32_t)(p * PA_STAGE_B + l_row * (PLDH * 2) + l_ch * 16),
                  &B[(size_t)(nb + l_row) * ldb + k0 + l_ch * 8]);
        CP_COMMIT();
    }

    for (int kt = 0; kt < PKT; kt++) {
        CP_WAIT2();
        __syncthreads();
        const int bi = kt & 3;
        const __half* Asb = Ash + bi * (128 * PLDH);
        const __half* Bsb = Bsh + bi * (128 * PLDH);
        uint32_t a[2][4];
#pragma unroll
        for (int mt = 0; mt < 2; mt++) {
            int rb = wm * 32 + mt * 16 + qr;
            a[mt][0] = *reinterpret_cast<const uint32_t*>(&Asb[rb * PLDH + 2 * qc]);
            a[mt][1] = *reinterpret_cast<const uint32_t*>(&Asb[(rb + 8) * PLDH + 2 * qc]);
            a[mt][2] = *reinterpret_cast<const uint32_t*>(&Asb[rb * PLDH + 2 * qc + 8]);
            a[mt][3] = *reinterpret_cast<const uint32_t*>(&Asb[(rb + 8) * PLDH + 2 * qc + 8]);
        }
#pragma unroll
        for (int nt = 0; nt < 8; nt++) {
            int ncol = wn * 64 + nt * 8 + qr;
            uint32_t b0 = *reinterpret_cast<const uint32_t*>(&Bsb[ncol * PLDH + 2 * qc]);
            uint32_t b1 = *reinterpret_cast<const uint32_t*>(&Bsb[ncol * PLDH + 2 * qc + 8]);
            mma_f16(cf[0][nt], a[0], b0, b1);
            mma_f16(cf[1][nt], a[1], b0, b1);
        }
        const int kn = kt + 3;
        if (kn < PKT) {
            const int st = kn & 3;
            const int k0 = kn * 16;
            cpasync16(sbA + (uint32_t)(st * PA_STAGE_B + l_row * (PLDH * 2) + l_ch * 16),
                      &A[(size_t)(mb + l_row) * lda + k0 + l_ch * 8]);
            cpasync16(sbB + (uint32_t)(st * PA_STAGE_B + l_row * (PLDH * 2) + l_ch * 16),
                      &B[(size_t)(nb + l_row) * ldb + k0 + l_ch * 8]);
        }
        CP_COMMIT();
    }

#pragma unroll
    for (int mt = 0; mt < 2; mt++)
#pragma unroll
        for (int nt = 0; nt < 8; nt++) {
            const int gcol = nb + wn * 64 + nt * 8 + 2 * qc;
            const int r0 = mb + wm * 32 + mt * 16 + qr;
            const float bv0 = bias ? bias[gcol] : 0.0f;
            const float bv1 = bias ? bias[gcol + 1] : 0.0f;
            if (OUT_HALF) {
                __half* C = (__half*)Cv;
                *reinterpret_cast<__half2*>(&C[(size_t)r0 * ldc + gcol]) =
                    __floats2half2_rn(cf[mt][nt][0] + bv0, cf[mt][nt][1] + bv1);
                *reinterpret_cast<__half2*>(&C[(size_t)(r0 + 8) * ldc + gcol]) =
                    __floats2half2_rn(cf[mt][nt][2] + bv0, cf[mt][nt][3] + bv1);
            } else {
                float* C = (float*)Cv;
                float2 v0 = make_float2(cf[mt][nt][0] + bv0, cf[mt][nt][1] + bv1);
                float2 v1 = make_float2(cf[mt][nt][2] + bv0, cf[mt][nt][3] + bv1);
                *reinterpret_cast<float2*>(&C[(size_t)r0 * ldc + gcol]) = v0;
                *reinterpret_cast<float2*>(&C[(size_t)(r0 + 8) * ldc + gcol]) = v1;
            }
        }
}

// ================== main fused fp16 mma kernel ============================
// Grid (8, 64). Block 256 (8 warps, 4m x 2n). BM=128, BN=128, BK=32,
// 4-stage cp.async. A = t1 half (t01h cols 768..), B = Bc[c] (scale baked).
#define BM 128
#define BN 128
#define BK 32
#define NJT 6
#define KTILES 24
#define LDH 40                      // 32 + 8 pad halves; 80B rows, conflict-free
#define A_STAGE_B (BM * LDH * 2)    // 10240 bytes

#define O_BS   (4 * A_STAGE_B)                 // 40960
#define O_ALS  (O_BS + 4 * A_STAGE_B)          // 81920
#define O_W2S  (O_ALS + H_DIM * 4)             // 84992
#define O_SCR  (O_W2S + 3 * H_DIM * 4)         // 94208
#define SMEM_SZ (O_SCR + BM * 3 * 4)           // 95744 bytes -> 2 blocks/SM

__global__ void __launch_bounds__(256, 2)
k_main_mma(const __half* __restrict__ t01h,   // (1024, 1536); t1 at col 768
           const __half* __restrict__ Bc,     // (64, 768 j, 768 k)
           const float* __restrict__ At,      // (1024, 768)
           const float* __restrict__ Al,      // (64, 768)
           const float* __restrict__ W2,      // (768, 3)
           const float* __restrict__ b2,
           float* __restrict__ out) {         // (1024, 64, 3)
    extern __shared__ char smc[];
    __half* Ash = reinterpret_cast<__half*>(smc);
    __half* Bsh = reinterpret_cast<__half*>(smc + O_BS);
    float* als = reinterpret_cast<float*>(smc + O_ALS);
    float* w2s = reinterpret_cast<float*>(smc + O_W2S);
    float* scr = reinterpret_cast<float*>(smc + O_SCR);
    const uint32_t sbA = smem_u32(Ash);
    const uint32_t sbB = smem_u32(Bsh);

    const int tid = threadIdx.x;
    const int lane = tid & 31, wid = tid >> 5;
    const int wm = wid & 3, wn = wid >> 2;
    const int qr = lane >> 2, qc = lane & 3;
    const int c = blockIdx.y;
    const int wbase = blockIdx.x * BM;

    for (int i = tid; i < H_DIM; i += 256) als[i] = Al[c * H_DIM + i];
    for (int i = tid; i < 3 * H_DIM; i += 256) w2s[i] = W2[i];
    for (int i = tid; i < BM * 3; i += 256) scr[i] = 0.0f;
    __syncthreads();

    const __half* Bcc = Bc + (size_t)c * H_DIM * H_DIM;
    const __half* A0 = t01h + H_DIM;    // t1 columns

    float sc[4][3];
#pragma unroll
    for (int i = 0; i < 4; i++)
#pragma unroll
        for (int k = 0; k < 3; k++) sc[i][k] = 0.0f;

    for (int jt = 0; jt < NJT; jt++) {
        const int jb = jt * BN;
        float cf[2][8][4];
#pragma unroll
        for (int mt = 0; mt < 2; mt++)
#pragma unroll
            for (int nt = 0; nt < 8; nt++)
#pragma unroll
                for (int r = 0; r < 4; r++) cf[mt][nt][r] = 0.0f;

        // ---- prologue: k-tiles 0..2 into stages 0..2 (2 chunks/thread/matrix) ----
#pragma unroll
        for (int p = 0; p < 3; p++) {
            const int k0 = p * BK;
#pragma unroll
            for (int i = 0; i < 2; i++) {
                int idx = tid + 256 * i;
                int row = idx >> 2, ch = idx & 3;
                cpasync16(sbA + (uint32_t)(p * A_STAGE_B + row * (LDH * 2) + ch * 16),
                          &A0[(size_t)(wbase + row) * TH_DIM + k0 + ch * 8]);
                cpasync16(sbB + (uint32_t)(p * A_STAGE_B + row * (LDH * 2) + ch * 16),
                          &Bcc[(size_t)(jb + row) * H_DIM + k0 + ch * 8]);
            }
            CP_COMMIT();
        }

        for (int kt = 0; kt < KTILES; kt++) {
            CP_WAIT2();
            __syncthreads();
            const int bi = kt & 3;
            const __half* Asb = Ash + bi * (A_STAGE_B / 2);
            const __half* Bsb = Bsh + bi * (A_STAGE_B / 2);
#pragma unroll
            for (int ks = 0; ks < 2; ks++) {
                const int ko = ks * 16;
                uint32_t a[2][4];
#pragma unroll
                for (int mt = 0; mt < 2; mt++) {
                    int rb = wm * 32 + mt * 16 + qr;
                    a[mt][0] = *reinterpret_cast<const uint32_t*>(&Asb[rb * LDH + ko + 2 * qc]);
                    a[mt][1] = *reinterpret_cast<const uint32_t*>(&Asb[(rb + 8) * LDH + ko + 2 * qc]);
                    a[mt][2] = *reinterpret_cast<const uint32_t*>(&Asb[rb * LDH + ko + 2 * qc + 8]);
                    a[mt][3] = *reinterpret_cast<const uint32_t*>(&Asb[(rb + 8) * LDH + ko + 2 * qc + 8]);
                }
#pragma unroll
                for (int nt = 0; nt < 8; nt++) {
                    int ncol = wn * 64 + nt * 8 + qr;
                    uint32_t b0 = *reinterpret_cast<const uint32_t*>(&Bsb[ncol * LDH + ko + 2 * qc]);
                    uint32_t b1 = *reinterpret_cast<const uint32_t*>(&Bsb[ncol * LDH + ko + 2 * qc + 8]);
                    mma_f16(cf[0][nt], a[0], b0, b1);
                    mma_f16(cf[1][nt], a[1], b0, b1);
                }
            }
            const int kn = kt + 3;
            if (kn < KTILES) {
                const int st = kn & 3;
                const int k0 = kn * BK;
#pragma unroll
                for (int i = 0; i < 2; i++) {
                    int idx = tid + 256 * i;
                    int row = idx >> 2, ch = idx & 3;
                    cpasync16(sbA + (uint32_t)(st * A_STAGE_B + row * (LDH * 2) + ch * 16),
                              &A0[(size_t)(wbase + row) * TH_DIM + k0 + ch * 8]);
                    cpasync16(sbB + (uint32_t)(st * A_STAGE_B + row * (LDH * 2) + ch * 16),
                              &Bcc[(size_t)(jb + row) * H_DIM + k0 + ch * 8]);
                }
            }
            CP_COMMIT();
        }

        // ---- fused epilogue for this j-tile ----
#pragma unroll
        for (int mt = 0; mt < 2; mt++) {
#pragma unroll
            for (int nt = 0; nt < 8; nt++) {
                const int gcol = jb + wn * 64 + nt * 8 + 2 * qc;
                const int row0 = wbase + wm * 32 + mt * 16 + qr;
                float2 at0 = __ldg(reinterpret_cast<const float2*>(&At[(size_t)row0 * H_DIM + gcol]));
                float2 at1 = __ldg(reinterpret_cast<const float2*>(&At[(size_t)(row0 + 8) * H_DIM + gcol]));
                const float al0 = als[gcol], al1 = als[gcol + 1];
                const float wa0 = w2s[gcol * 3 + 0], wa1 = w2s[gcol * 3 + 1], wa2 = w2s[gcol * 3 + 2];
                const float wb0 = w2s[gcol * 3 + 3], wb1 = w2s[gcol * 3 + 4], wb2 = w2s[gcol * 3 + 5];
                const float h00 = fmaxf(cf[mt][nt][0] + at0.x + al0, 0.0f);
                const float h01 = fmaxf(cf[mt][nt][1] + at0.y + al1, 0.0f);
                const float h10 = fmaxf(cf[mt][nt][2] + at1.x + al0, 0.0f);
                const float h11 = fmaxf(cf[mt][nt][3] + at1.y + al1, 0.0f);
                sc[mt * 2 + 0][0] += h00 * wa0 + h01 * wb0;
                sc[mt * 2 + 0][1] += h00 * wa1 + h01 * wb1;
                sc[mt * 2 + 0][2] += h00 * wa2 + h01 * wb2;
                sc[mt * 2 + 1][0] += h10 * wa0 + h11 * wb0;
                sc[mt * 2 + 1][1] += h10 * wa1 + h11 * wb1;
                sc[mt * 2 + 1][2] += h10 * wa2 + h11 * wb2;
            }
        }
    }

    // ---- reduce over qc lanes, then across n-warps via shared atomics ----
#pragma unroll
    for (int i = 0; i < 4; i++)
#pragma unroll
        for (int k = 0; k < 3; k++) {
            float v = sc[i][k];
            v += __shfl_xor_sync(0xffffffffu, v, 1);
            v += __shfl_xor_sync(0xffffffffu, v, 2);
            sc[i][k] = v;
        }
    if (qc == 0) {
#pragma unroll
        for (int i = 0; i < 4; i++) {
            int rl = wm * 32 + (i >> 1) * 16 + (i & 1) * 8 + qr;
            atomicAdd(&scr[rl * 3 + 0], sc[i][0]);
            atomicAdd(&scr[rl * 3 + 1], sc[i][1]);
            atomicAdd(&scr[rl * 3 + 2], sc[i][2]);
        }
    }
    __syncthreads();
    if (tid < BM) {
        const int row = wbase + tid;
        float* o = &out[(size_t)row * (C_NUM * 3) + c * 3];
        o[0] = scr[tid * 3 + 0] + __ldg(&b2[0]);
        o[1] = scr[tid * 3 + 1] + __ldg(&b2[1]);
        o[2] = scr[tid * 3 + 2] + __ldg(&b2[2]);
    }
}

// ---------------- launch ---------------------------------------------------
extern "C" void kernel_launch(void* const* d_in, const int* in_sizes, int n_in,
                              void* d_out, int out_size) {
    const float* tok_embs   = (const float*)d_in[0];   // (2048, 768)
    const int*   wmask      = (const int*)  d_in[1];   // (2048,)
    const float* label_embs = (const float*)d_in[3];   // (64, 768)
    const float* W_tok      = (const float*)d_in[4];   // (768, 1536)
    const float* b_tok      = (const float*)d_in[5];   // (1536,)
    const float* W_lab      = (const float*)d_in[6];   // (768, 1536)
    const float* b_lab      = (const float*)d_in[7];   // (1536,)
    const float* W1         = (const float*)d_in[8];   // (2304, 768)
    const float* b1         = (const float*)d_in[9];   // (768,)
    const float* W2         = (const float*)d_in[10];  // (768, 3)
    const float* b2         = (const float*)d_in[11];  // (3,)
    float* out = (float*)d_out;                        // (1024, 64, 3)

    float *lbp, *At, *Al, *W1pT;
    __half *weh, *WtokT, *W1tT, *t01h, *Bc;
    cudaGetSymbolAddress((void**)&lbp,   g_lb);
    cudaGetSymbolAddress((void**)&At,    g_At);
    cudaGetSymbolAddress((void**)&Al,    g_Al);
    cudaGetSymbolAddress((void**)&W1pT,  g_W1pT);
    cudaGetSymbolAddress((void**)&weh,   g_weh);
    cudaGetSymbolAddress((void**)&WtokT, g_WtokT);
    cudaGetSymbolAddress((void**)&W1tT,  g_W1tT);
    cudaGetSymbolAddress((void**)&t01h,  g_t01h);
    cudaGetSymbolAddress((void**)&Bc,    g_Bc);

    // idempotent, deterministic — no static guards (harness rule)
    cudaFuncSetAttribute(k_main_mma, cudaFuncAttributeMaxDynamicSharedMemorySize, SMEM_SZ);
    cudaFuncSetAttribute(k_gemm_h<true>, cudaFuncAttributeMaxDynamicSharedMemorySize, PSMEM_SZ);
    cudaFuncSetAttribute(k_gemm_h<false>, cudaFuncAttributeMaxDynamicSharedMemorySize, PSMEM_SZ);

    // 0) weight prep (independent)
    k_transpose768<<<dim3(H_DIM / 32, H_DIM / 32), dim3(32, 8)>>>(
        W1 + (size_t)2 * H_DIM * H_DIM, W1pT);
    k_transpose_h<<<dim3(TH_DIM / 32, H_DIM / 32), dim3(32, 8)>>>(
        W_tok, WtokT, H_DIM, TH_DIM);
    k_transpose_h<<<dim3(H_DIM / 32, H_DIM / 32), dim3(32, 8)>>>(
        W1, W1tT, H_DIM, H_DIM);

    // 1) scatter pooling (last token index wins per word), half output
    k_init_winner<<<(W_NUM + 255) / 256, 256>>>();
    k_scatter<<<(L_TOK + 255) / 256, 256>>>(wmask);
    k_build_we_h<<<W_NUM, 256>>>(tok_embs);

    // 2) lb = label_embs @ W_lab + b_lab (64 x 1536, fp32 SIMT)
    k_gemm_bias<<<dim3(1, TH_DIM / 64), 256>>>(
        label_embs, H_DIM, W_lab, TH_DIM, b_lab, lbp, TH_DIM, H_DIM);

    // 3) Bc[c][j][k] = half(lb1[c,k] * W1p[k,j])
    k_make_bc<<<dim3(H_DIM / 8, C_NUM), 256>>>();

    // 4) t01h = half(weh @ W_tok + b_tok)   (1024 x 1536, fp16 mma)
    k_gemm_h<true><<<dim3(W_NUM / 128, TH_DIM / 128), 256, PSMEM_SZ>>>(
        weh, H_DIM, WtokT, H_DIM, b_tok, t01h, TH_DIM);

    // 5) At = t0h @ W1_t + b1              (1024 x 768 fp32, fp16 mma)
    k_gemm_h<false><<<dim3(W_NUM / 128, H_DIM / 128), 256, PSMEM_SZ>>>(
        t01h, TH_DIM, W1tT, H_DIM, b1, At, H_DIM);

    // 6) Al = lb0 @ W1_l                   (64 x 768, fp32 SIMT)
    k_gemm_bias<<<dim3(1, H_DIM / 64), 256>>>(
        lbp, TH_DIM, W1 + (size_t)H_DIM * H_DIM, H_DIM, nullptr, Al, H_DIM, H_DIM);

    // 7) fused fp16 mma prod-GEMM + relu + W2 contraction -> scores
    k_main_mma<<<dim3(W_NUM / BM, C_NUM), 256, SMEM_SZ>>>(
        t01h, Bc, At, Al, W2, b2, out);

    (void)in_sizes; (void)n_in; (void)out_size;
}

// round 11
// speedup vs baseline: 5.0687x; 1.0184x over previous
#include <cuda_runtime.h>
#include <cuda_fp16.h>
#include <cstdint>

// Problem constants (fixed shapes for GLiNERLinkerPooler_14671608283278)
#define L_TOK 2048
#define H_DIM 768
#define W_NUM 1024
#define C_NUM 64
#define TH_DIM 1536   // 2*H
// W1 is (2304, 768): rows [0,768)=W1_t, [768,1536)=W1_l, [1536,2304)=W1_p

// ---------------- device scratch (no allocations allowed) ----------------
__device__ int    g_winner[W_NUM];
__device__ __half g_weh[W_NUM * H_DIM];           // 1.5 MB half(we)
__device__ __half g_WtokT[TH_DIM * H_DIM];        // 2.3 MB half(W_tok^T) [n][k]
__device__ __half g_W1tT[H_DIM * H_DIM];          // 1.1 MB half(W1_t^T)  [n][k]
__device__ __half g_t01h[W_NUM * TH_DIM];         // 3 MB   half(t) [w][2H]
__device__ float  g_lb[C_NUM * TH_DIM];           // 0.4 MB
__device__ __half g_Ath[W_NUM * H_DIM];           // 1.5 MB half(t0@W1_t + b1) [w][j]
__device__ float  g_Al[C_NUM * H_DIM];            // 0.2 MB
__device__ float  g_W1pT[H_DIM * H_DIM];          // 2.3 MB (W1p^T fp32: [j][h])
__device__ __half g_Bc[(size_t)C_NUM * H_DIM * H_DIM]; // 75.5 MB half(lb1[c,k]*W1p[k,j]) [c][j][k]

// ---------------- helpers -------------------------------------------------
// m16n8k16 fp16 MMA, f32 accumulate (sm_80+ baseline PTX)
__device__ __forceinline__ void mma_f16(float* c, const uint32_t* a,
                                        uint32_t b0, uint32_t b1) {
    asm volatile(
        "mma.sync.aligned.m16n8k16.row.col.f32.f16.f16.f32 "
        "{%0,%1,%2,%3}, {%4,%5,%6,%7}, {%8,%9}, {%0,%1,%2,%3};"
        : "+f"(c[0]), "+f"(c[1]), "+f"(c[2]), "+f"(c[3])
        : "r"(a[0]), "r"(a[1]), "r"(a[2]), "r"(a[3]), "r"(b0), "r"(b1));
}
__device__ __forceinline__ uint32_t smem_u32(const void* p) {
    uint32_t a;
    asm("{ .reg .u64 t; cvta.to.shared.u64 t, %1; cvt.u32.u64 %0, t; }" : "=r"(a) : "l"(p));
    return a;
}
__device__ __forceinline__ void cpasync16(uint32_t dst, const void* src) {
    asm volatile("cp.async.cg.shared.global [%0], [%1], 16;" :: "r"(dst), "l"(src));
}
#define CP_COMMIT()  asm volatile("cp.async.commit_group;" ::: "memory")
#define CP_WAIT1()   asm volatile("cp.async.wait_group 1;" ::: "memory")
#define CP_WAIT2()   asm volatile("cp.async.wait_group 2;" ::: "memory")

// ---------------- scatter pooling (last token index wins) ----------------
__global__ void k_init_winner() {
    int w = blockIdx.x * blockDim.x + threadIdx.x;
    if (w < W_NUM) g_winner[w] = -1;
}
__global__ void k_scatter(const int* __restrict__ wmask) {
    int l = blockIdx.x * blockDim.x + threadIdx.x;
    if (l < L_TOK) {
        int v = wmask[l];
        if (v > 0 && v - 1 < W_NUM) atomicMax(&g_winner[v - 1], l);
    }
}
__global__ void k_build_we_h(const float* __restrict__ tok_embs) {
    int w = blockIdx.x;
    int src = g_winner[w];
    __half* dst = &g_weh[w * H_DIM];
    if (src >= 0) {
        const float* s = &tok_embs[(size_t)src * H_DIM];
        for (int h = threadIdx.x; h < H_DIM; h += blockDim.x) dst[h] = __float2half(s[h]);
    } else {
        for (int h = threadIdx.x; h < H_DIM; h += blockDim.x) dst[h] = __float2half(0.0f);
    }
}

// ---------------- transposes ----------------------------------------------
// fp32 (h,j)->(j,h), 768x768
__global__ void k_transpose768(const float* __restrict__ src, float* __restrict__ dst) {
    __shared__ float tl[32][33];
    int j0 = blockIdx.x * 32, h0 = blockIdx.y * 32;
    for (int dy = threadIdx.y; dy < 32; dy += 8)
        tl[dy][threadIdx.x] = src[(size_t)(h0 + dy) * H_DIM + j0 + threadIdx.x];
    __syncthreads();
    for (int dy = threadIdx.y; dy < 32; dy += 8)
        dst[(size_t)(j0 + dy) * H_DIM + h0 + threadIdx.x] = tl[threadIdx.x][dy];
}
// fp32 src[K][N] -> half dst[N][K]
__global__ void k_transpose_h(const float* __restrict__ src, __half* __restrict__ dst,
                              int K, int N) {
    __shared__ float tl[32][33];
    int n0 = blockIdx.x * 32, k0 = blockIdx.y * 32;
    for (int dy = threadIdx.y; dy < 32; dy += 8)
        tl[dy][threadIdx.x] = src[(size_t)(k0 + dy) * N + n0 + threadIdx.x];
    __syncthreads();
    for (int dy = threadIdx.y; dy < 32; dy += 8)
        dst[(size_t)(n0 + dy) * K + k0 + threadIdx.x] = __float2half(tl[threadIdx.x][dy]);
}

// ---------------- Bc[c][j][k] = half(lb1[c,k] * W1pT[j,k]) ----------------
__global__ void k_make_bc() {
    const int c = blockIdx.y;
    const int j0 = blockIdx.x * 8;
    const float* lb1 = &g_lb[(size_t)c * TH_DIM + H_DIM];
    __half2* out = reinterpret_cast<__half2*>(&g_Bc[((size_t)c * H_DIM + j0) * H_DIM]);
#pragma unroll
    for (int i = 0; i < 12; i++) {
        int slot = threadIdx.x + 256 * i;
        int jj = slot / (H_DIM / 2), kk = slot % (H_DIM / 2);
        float2 w = *reinterpret_cast<const float2*>(&g_W1pT[(size_t)(j0 + jj) * H_DIM + kk * 2]);
        float2 s = *reinterpret_cast<const float2*>(&lb1[kk * 2]);
        out[slot] = __floats2half2_rn(w.x * s.x, w.y * s.y);
    }
}

// ---------------- SIMT fp32 GEMM (small label-side GEMMs only) ------------
__global__ void k_gemm_bias(const float* __restrict__ A, int lda,
                            const float* __restrict__ B, int ldb,
                            const float* __restrict__ bias,
                            float* __restrict__ C, int ldc, int K) {
    __shared__ float As[16][64];
    __shared__ float Bs[16][64];
    const int tid = threadIdx.x;
    const int tx = tid & 15;
    const int ty = tid >> 4;
    const int mbase = blockIdx.x * 64;
    const int nbase = blockIdx.y * 64;

    float acc[4][4] = {};
    const int lw = tid >> 2, lkq = tid & 3;
    const int lkk = tid >> 4, lj4 = tid & 15;

    for (int k0 = 0; k0 < K; k0 += 16) {
        float4 va = *reinterpret_cast<const float4*>(&A[(size_t)(mbase + lw) * lda + k0 + lkq * 4]);
        As[lkq * 4 + 0][lw] = va.x;
        As[lkq * 4 + 1][lw] = va.y;
        As[lkq * 4 + 2][lw] = va.z;
        As[lkq * 4 + 3][lw] = va.w;
        *reinterpret_cast<float4*>(&Bs[lkk][lj4 * 4]) =
            *reinterpret_cast<const float4*>(&B[(size_t)(k0 + lkk) * ldb + nbase + lj4 * 4]);
        __syncthreads();
#pragma unroll
        for (int kk = 0; kk < 16; kk++) {
            float4 a4 = *reinterpret_cast<const float4*>(&As[kk][ty * 4]);
            float4 b4 = *reinterpret_cast<const float4*>(&Bs[kk][tx * 4]);
            float a[4] = {a4.x, a4.y, a4.z, a4.w};
            float b[4] = {b4.x, b4.y, b4.z, b4.w};
#pragma unroll
            for (int i = 0; i < 4; i++)
#pragma unroll
                for (int j = 0; j < 4; j++)
                    acc[i][j] = fmaf(a[i], b[j], acc[i][j]);
        }
        __syncthreads();
    }
#pragma unroll
    for (int j = 0; j < 4; j++) {
        int col = nbase + tx * 4 + j;
        float bv = bias ? bias[col] : 0.0f;
#pragma unroll
        for (int i = 0; i < 4; i++) {
            int row = mbase + ty * 4 + i;
            C[(size_t)row * ldc + col] = acc[i][j] + bv;
        }
    }
}

// ================== generic fp16 mma GEMM (prologue) ======================
// C[M,N] = A[M,K]h @ B[N,K]h^T + bias (half C). BM=BN=128, BK=16,
// 4-stage cp.async, K fixed at 768.
#define PLDH 24
#define PKT  48
#define PA_STAGE_B (128 * PLDH * 2)   // 6144 bytes
#define PSMEM_SZ (8 * PA_STAGE_B)     // 49152 bytes

__global__ void __launch_bounds__(256)
k_gemm_h(const __half* __restrict__ A, int lda,
         const __half* __restrict__ B, int ldb,
         const float* __restrict__ bias,
         __half* __restrict__ C, int ldc) {
    extern __shared__ char psm[];
    __half* Ash = reinterpret_cast<__half*>(psm);
    __half* Bsh = reinterpret_cast<__half*>(psm + 4 * PA_STAGE_B);
    const uint32_t sbA = smem_u32(Ash);
    const uint32_t sbB = smem_u32(Bsh);

    const int tid = threadIdx.x;
    const int lane = tid & 31, wid = tid >> 5;
    const int wm = wid & 3, wn = wid >> 2;
    const int qr = lane >> 2, qc = lane & 3;
    const int mb = blockIdx.x * 128;
    const int nb = blockIdx.y * 128;
    const int l_row = tid >> 1, l_ch = tid & 1;

    float cf[2][8][4];
#pragma unroll
    for (int mt = 0; mt < 2; mt++)
#pragma unroll
        for (int nt = 0; nt < 8; nt++)
#pragma unroll
            for (int r = 0; r < 4; r++) cf[mt][nt][r] = 0.0f;

#pragma unroll
    for (int p = 0; p < 3; p++) {
        const int k0 = p * 16;
        cpasync16(sbA + (uint32_t)(p * PA_STAGE_B + l_row * (PLDH * 2) + l_ch * 16),
                  &A[(size_t)(mb + l_row) * lda + k0 + l_ch * 8]);
        cpasync16(sbB + (uint32_t)(p * PA_STAGE_B + l_row * (PLDH * 2) + l_ch * 16),
                  &B[(size_t)(nb + l_row) * ldb + k0 + l_ch * 8]);
        CP_COMMIT();
    }

    for (int kt = 0; kt < PKT; kt++) {
        CP_WAIT2();
        __syncthreads();
        const int bi = kt & 3;
        const __half* Asb = Ash + bi * (128 * PLDH);
        const __half* Bsb = Bsh + bi * (128 * PLDH);
        uint32_t a[2][4];
#pragma unroll
        for (int mt = 0; mt < 2; mt++) {
            int rb = wm * 32 + mt * 16 + qr;
            a[mt][0] = *reinterpret_cast<const uint32_t*>(&Asb[rb * PLDH + 2 * qc]);
            a[mt][1] = *reinterpret_cast<const uint32_t*>(&Asb[(rb + 8) * PLDH + 2 * qc]);
            a[mt][2] = *reinterpret_cast<const uint32_t*>(&Asb[rb * PLDH + 2 * qc + 8]);
            a[mt][3] = *reinterpret_cast<const uint32_t*>(&Asb[(rb + 8) * PLDH + 2 * qc + 8]);
        }
#pragma unroll
        for (int nt = 0; nt < 8; nt++) {
            int ncol = wn * 64 + nt * 8 + qr;
            uint32_t b0 = *reinterpret_cast<const uint32_t*>(&Bsb[ncol * PLDH + 2 * qc]);
            uint32_t b1 = *reinterpret_cast<const uint32_t*>(&Bsb[ncol * PLDH + 2 * qc + 8]);
            mma_f16(cf[0][nt], a[0], b0, b1);
            mma_f16(cf[1][nt], a[1], b0, b1);
        }
        const int kn = kt + 3;
        if (kn < PKT) {
            const int st = kn & 3;
            const int k0 = kn * 16;
            cpasync16(sbA + (uint32_t)(st * PA_STAGE_B + l_row * (PLDH * 2) + l_ch * 16),
                      &A[(size_t)(mb + l_row) * lda + k0 + l_ch * 8]);
            cpasync16(sbB + (uint32_t)(st * PA_STAGE_B + l_row * (PLDH * 2) + l_ch * 16),
                      &B[(size_t)(nb + l_row) * ldb + k0 + l_ch * 8]);
        }
        CP_COMMIT();
    }

#pragma unroll
    for (int mt = 0; mt < 2; mt++)
#pragma unroll
        for (int nt = 0; nt < 8; nt++) {
            const int gcol = nb + wn * 64 + nt * 8 + 2 * qc;
            const int r0 = mb + wm * 32 + mt * 16 + qr;
            const float bv0 = bias ? bias[gcol] : 0.0f;
            const float bv1 = bias ? bias[gcol + 1] : 0.0f;
            *reinterpret_cast<__half2*>(&C[(size_t)r0 * ldc + gcol]) =
                __floats2half2_rn(cf[mt][nt][0] + bv0, cf[mt][nt][1] + bv1);
            *reinterpret_cast<__half2*>(&C[(size_t)(r0 + 8) * ldc + gcol]) =
                __floats2half2_rn(cf[mt][nt][2] + bv0, cf[mt][nt][3] + bv1);
        }
}

// ================== main fused fp16 mma kernel ============================
// Grid (8, 64). Block 256 (8 warps, 4m x 2n). BM=128, BN=128, BK=32,
// 3-stage cp.async + smem At prefetch (half, streamed during kts 0..7).
#define BM 128
#define BN 128
#define BK 32
#define NJT 6
#define KTILES 24
#define LDH 40                      // 32 + 8 pad halves; 80B rows, conflict-free
#define A_STAGE_B (BM * LDH * 2)    // 10240 bytes
#define LDAT 136                    // At row: 128 + 8 pad halves = 272 B (conflict-free)

#define O_BS   (3 * A_STAGE_B)                 // 30720
#define O_ATS  (O_BS + 3 * A_STAGE_B)          // 61440
#define O_ALS  (O_ATS + BM * LDAT * 2)         // 96256
#define O_W2S  (O_ALS + H_DIM * 4)             // 99328
#define O_SCR  (O_W2S + 3 * H_DIM * 4)         // 108544
#define SMEM_SZ (O_SCR + BM * 3 * 4)           // 110080 bytes -> 2 blocks/SM

__global__ void __launch_bounds__(256, 2)
k_main_mma(const __half* __restrict__ t01h,   // (1024, 1536); t1 at col 768
           const __half* __restrict__ Bc,     // (64, 768 j, 768 k)
           const __half* __restrict__ Ath,    // (1024, 768) half
           const float* __restrict__ Al,      // (64, 768)
           const float* __restrict__ W2,      // (768, 3)
           const float* __restrict__ b2,
           float* __restrict__ out) {         // (1024, 64, 3)
    extern __shared__ char smc[];
    __half* Ash = reinterpret_cast<__half*>(smc);
    __half* Bsh = reinterpret_cast<__half*>(smc + O_BS);
    __half* Ats = reinterpret_cast<__half*>(smc + O_ATS);
    float* als = reinterpret_cast<float*>(smc + O_ALS);
    float* w2s = reinterpret_cast<float*>(smc + O_W2S);
    float* scr = reinterpret_cast<float*>(smc + O_SCR);
    const uint32_t sbA = smem_u32(Ash);
    const uint32_t sbB = smem_u32(Bsh);
    const uint32_t sbT = smem_u32(Ats);

    const int tid = threadIdx.x;
    const int lane = tid & 31, wid = tid >> 5;
    const int wm = wid & 3, wn = wid >> 2;
    const int qr = lane >> 2, qc = lane & 3;
    const int c = blockIdx.y;
    const int wbase = blockIdx.x * BM;

    for (int i = tid; i < H_DIM; i += 256) als[i] = Al[c * H_DIM + i];
    for (int i = tid; i < 3 * H_DIM; i += 256) w2s[i] = W2[i];
    for (int i = tid; i < BM * 3; i += 256) scr[i] = 0.0f;
    __syncthreads();

    const __half* Bcc = Bc + (size_t)c * H_DIM * H_DIM;
    const __half* A0 = t01h + H_DIM;    // t1 columns

    float sc[4][3];
#pragma unroll
    for (int i = 0; i < 4; i++)
#pragma unroll
        for (int k = 0; k < 3; k++) sc[i][k] = 0.0f;

    for (int jt = 0; jt < NJT; jt++) {
        const int jb = jt * BN;
        float cf[2][8][4];
#pragma unroll
        for (int mt = 0; mt < 2; mt++)
#pragma unroll
            for (int nt = 0; nt < 8; nt++)
#pragma unroll
                for (int r = 0; r < 4; r++) cf[mt][nt][r] = 0.0f;

        // ---- prologue: k-tiles 0..1 into stages 0..1 (2 chunks/thread/matrix) ----
#pragma unroll
        for (int p = 0; p < 2; p++) {
            const int k0 = p * BK;
#pragma unroll
            for (int i = 0; i < 2; i++) {
                int idx = tid + 256 * i;
                int row = idx >> 2, ch = idx & 3;
                cpasync16(sbA + (uint32_t)(p * A_STAGE_B + row * (LDH * 2) + ch * 16),
                          &A0[(size_t)(wbase + row) * TH_DIM + k0 + ch * 8]);
                cpasync16(sbB + (uint32_t)(p * A_STAGE_B + row * (LDH * 2) + ch * 16),
                          &Bcc[(size_t)(jb + row) * H_DIM + k0 + ch * 8]);
            }
            CP_COMMIT();
        }

        for (int kt = 0; kt < KTILES; kt++) {
            CP_WAIT1();
            __syncthreads();
            const int bi = kt % 3;
            const __half* Asb = Ash + bi * (A_STAGE_B / 2);
            const __half* Bsb = Bsh + bi * (A_STAGE_B / 2);
#pragma unroll
            for (int ks = 0; ks < 2; ks++) {
                const int ko = ks * 16;
                uint32_t a[2][4];
#pragma unroll
                for (int mt = 0; mt < 2; mt++) {
                    int rb = wm * 32 + mt * 16 + qr;
                    a[mt][0] = *reinterpret_cast<const uint32_t*>(&Asb[rb * LDH + ko + 2 * qc]);
                    a[mt][1] = *reinterpret_cast<const uint32_t*>(&Asb[(rb + 8) * LDH + ko + 2 * qc]);
                    a[mt][2] = *reinterpret_cast<const uint32_t*>(&Asb[rb * LDH + ko + 2 * qc + 8]);
                    a[mt][3] = *reinterpret_cast<const uint32_t*>(&Asb[(rb + 8) * LDH + ko + 2 * qc + 8]);
                }
#pragma unroll
                for (int nt = 0; nt < 8; nt++) {
                    int ncol = wn * 64 + nt * 8 + qr;
                    uint32_t b0 = *reinterpret_cast<const uint32_t*>(&Bsb[ncol * LDH + ko + 2 * qc]);
                    uint32_t b1 = *reinterpret_cast<const uint32_t*>(&Bsb[ncol * LDH + ko + 2 * qc + 8]);
                    mma_f16(cf[0][nt], a[0], b0, b1);
                    mma_f16(cf[1][nt], a[1], b0, b1);
                }
            }
            // ---- issue k-tile kt+2 + one At chunk per thread (kts 0..7) ----
            const int kn = kt + 2;
            if (kn < KTILES) {
                const int st = kn % 3;
                const int k0 = kn * BK;
#pragma unroll
                for (int i = 0; i < 2; i++) {
                    int idx = tid + 256 * i;
                    int row = idx >> 2, ch = idx & 3;
                    cpasync16(sbA + (uint32_t)(st * A_STAGE_B + row * (LDH * 2) + ch * 16),
                              &A0[(size_t)(wbase + row) * TH_DIM + k0 + ch * 8]);
                    cpasync16(sbB + (uint32_t)(st * A_STAGE_B + row * (LDH * 2) + ch * 16),
                              &Bcc[(size_t)(jb + row) * H_DIM + k0 + ch * 8]);
                }
            }
            if (kt < 8) {
                // At j-tile: 128 rows x 16 chunks of 16B; 256 chunks per kt
                int cidx = tid + 256 * kt;
                int row = cidx >> 4, ch = cidx & 15;
                cpasync16(sbT + (uint32_t)(row * (LDAT * 2) + ch * 16),
                          &Ath[(size_t)(wbase + row) * H_DIM + jb + ch * 8]);
            }
            CP_COMMIT();
        }

        // ---- fused epilogue for this j-tile (At from smem) ----
#pragma unroll
        for (int mt = 0; mt < 2; mt++) {
#pragma unroll
            for (int nt = 0; nt < 8; nt++) {
                const int lcol = wn * 64 + nt * 8 + 2 * qc;
                const int gcol = jb + lcol;
                const int lr0 = wm * 32 + mt * 16 + qr;
                float2 at0 = __half22float2(
                    *reinterpret_cast<const __half2*>(&Ats[lr0 * LDAT + lcol]));
                float2 at1 = __half22float2(
                    *reinterpret_cast<const __half2*>(&Ats[(lr0 + 8) * LDAT + lcol]));
                const float al0 = als[gcol], al1 = als[gcol + 1];
                const float wa0 = w2s[gcol * 3 + 0], wa1 = w2s[gcol * 3 + 1], wa2 = w2s[gcol * 3 + 2];
                const float wb0 = w2s[gcol * 3 + 3], wb1 = w2s[gcol * 3 + 4], wb2 = w2s[gcol * 3 + 5];
                const float h00 = fmaxf(cf[mt][nt][0] + at0.x + al0, 0.0f);
                const float h01 = fmaxf(cf[mt][nt][1] + at0.y + al1, 0.0f);
                const float h10 = fmaxf(cf[mt][nt][2] + at1.x + al0, 0.0f);
                const float h11 = fmaxf(cf[mt][nt][3] + at1.y + al1, 0.0f);
                sc[mt * 2 + 0][0] += h00 * wa0 + h01 * wb0;
                sc[mt * 2 + 0][1] += h00 * wa1 + h01 * wb1;
                sc[mt * 2 + 0][2] += h00 * wa2 + h01 * wb2;
                sc[mt * 2 + 1][0] += h10 * wa0 + h11 * wb0;
                sc[mt * 2 + 1][1] += h10 * wa1 + h11 * wb1;
                sc[mt * 2 + 1][2] += h10 * wa2 + h11 * wb2;
            }
        }
        __syncthreads();   // all epilogue reads of Ats done before next j-tile overwrites
    }

    // ---- reduce over qc lanes, then across n-warps via shared atomics ----
#pragma unroll
    for (int i = 0; i < 4; i++)
#pragma unroll
        for (int k = 0; k < 3; k++) {
            float v = sc[i][k];
            v += __shfl_xor_sync(0xffffffffu, v, 1);
            v += __shfl_xor_sync(0xffffffffu, v, 2);
            sc[i][k] = v;
        }
    if (qc == 0) {
#pragma unroll
        for (int i = 0; i < 4; i++) {
            int rl = wm * 32 + (i >> 1) * 16 + (i & 1) * 8 + qr;
            atomicAdd(&scr[rl * 3 + 0], sc[i][0]);
            atomicAdd(&scr[rl * 3 + 1], sc[i][1]);
            atomicAdd(&scr[rl * 3 + 2], sc[i][2]);
        }
    }
    __syncthreads();
    if (tid < BM) {
        const int row = wbase + tid;
        float* o = &out[(size_t)row * (C_NUM * 3) + c * 3];
        o[0] = scr[tid * 3 + 0] + __ldg(&b2[0]);
        o[1] = scr[tid * 3 + 1] + __ldg(&b2[1]);
        o[2] = scr[tid * 3 + 2] + __ldg(&b2[2]);
    }
}

// ---------------- launch ---------------------------------------------------
extern "C" void kernel_launch(void* const* d_in, const int* in_sizes, int n_in,
                              void* d_out, int out_size) {
    const float* tok_embs   = (const float*)d_in[0];   // (2048, 768)
    const int*   wmask      = (const int*)  d_in[1];   // (2048,)
    const float* label_embs = (const float*)d_in[3];   // (64, 768)
    const float* W_tok      = (const float*)d_in[4];   // (768, 1536)
    const float* b_tok      = (const float*)d_in[5];   // (1536,)
    const float* W_lab      = (const float*)d_in[6];   // (768, 1536)
    const float* b_lab      = (const float*)d_in[7];   // (1536,)
    const float* W1         = (const float*)d_in[8];   // (2304, 768)
    const float* b1         = (const float*)d_in[9];   // (768,)
    const float* W2         = (const float*)d_in[10];  // (768, 3)
    const float* b2         = (const float*)d_in[11];  // (3,)
    float* out = (float*)d_out;                        // (1024, 64, 3)

    float *lbp, *Al, *W1pT;
    __half *weh, *WtokT, *W1tT, *t01h, *Ath, *Bc;
    cudaGetSymbolAddress((void**)&lbp,   g_lb);
    cudaGetSymbolAddress((void**)&Ath,   g_Ath);
    cudaGetSymbolAddress((void**)&Al,    g_Al);
    cudaGetSymbolAddress((void**)&W1pT,  g_W1pT);
    cudaGetSymbolAddress((void**)&weh,   g_weh);
    cudaGetSymbolAddress((void**)&WtokT, g_WtokT);
    cudaGetSymbolAddress((void**)&W1tT,  g_W1tT);
    cudaGetSymbolAddress((void**)&t01h,  g_t01h);
    cudaGetSymbolAddress((void**)&Bc,    g_Bc);

    // idempotent, deterministic — no static guards (harness rule)
    cudaFuncSetAttribute(k_main_mma, cudaFuncAttributeMaxDynamicSharedMemorySize, SMEM_SZ);
    cudaFuncSetAttribute(k_gemm_h, cudaFuncAttributeMaxDynamicSharedMemorySize, PSMEM_SZ);

    // 0) weight prep (independent)
    k_transpose768<<<dim3(H_DIM / 32, H_DIM / 32), dim3(32, 8)>>>(
        W1 + (size_t)2 * H_DIM * H_DIM, W1pT);
    k_transpose_h<<<dim3(TH_DIM / 32, H_DIM / 32), dim3(32, 8)>>>(
        W_tok, WtokT, H_DIM, TH_DIM);
    k_transpose_h<<<dim3(H_DIM / 32, H_DIM / 32), dim3(32, 8)>>>(
        W1, W1tT, H_DIM, H_DIM);

    // 1) scatter pooling (last token index wins per word), half output
    k_init_winner<<<(W_NUM + 255) / 256, 256>>>();
    k_scatter<<<(L_TOK + 255) / 256, 256>>>(wmask);
    k_build_we_h<<<W_NUM, 256>>>(tok_embs);

    // 2) lb = label_embs @ W_lab + b_lab (64 x 1536, fp32 SIMT)
    k_gemm_bias<<<dim3(1, TH_DIM / 64), 256>>>(
        label_embs, H_DIM, W_lab, TH_DIM, b_lab, lbp, TH_DIM, H_DIM);

    // 3) Bc[c][j][k] = half(lb1[c,k] * W1p[k,j])
    k_make_bc<<<dim3(H_DIM / 8, C_NUM), 256>>>();

    // 4) t01h = half(weh @ W_tok + b_tok)   (1024 x 1536, fp16 mma)
    k_gemm_h<<<dim3(W_NUM / 128, TH_DIM / 128), 256, PSMEM_SZ>>>(
        weh, H_DIM, WtokT, H_DIM, b_tok, t01h, TH_DIM);

    // 5) Ath = half(t0h @ W1_t + b1)        (1024 x 768, fp16 mma)
    k_gemm_h<<<dim3(W_NUM / 128, H_DIM / 128), 256, PSMEM_SZ>>>(
        t01h, TH_DIM, W1tT, H_DIM, b1, Ath, H_DIM);

    // 6) Al = lb0 @ W1_l                    (64 x 768, fp32 SIMT)
    k_gemm_bias<<<dim3(1, H_DIM / 64), 256>>>(
        lbp, TH_DIM, W1 + (size_t)H_DIM * H_DIM, H_DIM, nullptr, Al, H_DIM, H_DIM);

    // 7) fused fp16 mma prod-GEMM + relu + W2 contraction -> scores
    k_main_mma<<<dim3(W_NUM / BM, C_NUM), 256, SMEM_SZ>>>(
        t01h, Bc, Ath, Al, W2, b2, out);

    (void)in_sizes; (void)n_in; (void)out_size;
}

// round 12
// speedup vs baseline: 5.4480x; 1.0748x over previous
#include <cuda_runtime.h>
#include <cuda_fp16.h>
#include <cstdint>

// Problem constants (fixed shapes for GLiNERLinkerPooler_14671608283278)
#define L_TOK 2048
#define H_DIM 768
#define W_NUM 1024
#define C_NUM 64
#define TH_DIM 1536   // 2*H
// W1 is (2304, 768): rows [0,768)=W1_t, [768,1536)=W1_l, [1536,2304)=W1_p

// ---------------- device scratch (no allocations allowed) ----------------
__device__ int    g_winner[W_NUM];
__device__ __half g_weh[W_NUM * H_DIM];           // 1.5 MB half(we)
__device__ __half g_WtokT[TH_DIM * H_DIM];        // 2.3 MB half(W_tok^T) [n][k]
__device__ __half g_W1tT[H_DIM * H_DIM];          // 1.1 MB half(W1_t^T)  [n][k]
__device__ __half g_W1pTh[H_DIM * H_DIM];         // 1.1 MB half(W1_p^T)  [j][h]
__device__ __half g_t01h[W_NUM * TH_DIM];         // 3 MB   half(t) [w][2H]
__device__ float  g_lb[C_NUM * TH_DIM];           // 0.4 MB
__device__ __half g_Ath[W_NUM * H_DIM];           // 1.5 MB half(t0@W1_t + b1) [w][j]
__device__ float  g_Al[C_NUM * H_DIM];            // 0.2 MB

// ---------------- helpers -------------------------------------------------
// m16n8k16 fp16 MMA, f32 accumulate (sm_80+ baseline PTX)
__device__ __forceinline__ void mma_f16(float* c, const uint32_t* a,
                                        uint32_t b0, uint32_t b1) {
    asm volatile(
        "mma.sync.aligned.m16n8k16.row.col.f32.f16.f16.f32 "
        "{%0,%1,%2,%3}, {%4,%5,%6,%7}, {%8,%9}, {%0,%1,%2,%3};"
        : "+f"(c[0]), "+f"(c[1]), "+f"(c[2]), "+f"(c[3])
        : "r"(a[0]), "r"(a[1]), "r"(a[2]), "r"(a[3]), "r"(b0), "r"(b1));
}
__device__ __forceinline__ uint32_t smem_u32(const void* p) {
    uint32_t a;
    asm("{ .reg .u64 t; cvta.to.shared.u64 t, %1; cvt.u32.u64 %0, t; }" : "=r"(a) : "l"(p));
    return a;
}
__device__ __forceinline__ void cpasync16(uint32_t dst, const void* src) {
    asm volatile("cp.async.cg.shared.global [%0], [%1], 16;" :: "r"(dst), "l"(src));
}
__device__ __forceinline__ uint32_t hmul2u(uint32_t a, uint32_t s) {
    __half2 r = __hmul2(*reinterpret_cast<__half2*>(&a), *reinterpret_cast<__half2*>(&s));
    return *reinterpret_cast<uint32_t*>(&r);
}
#define CP_COMMIT()  asm volatile("cp.async.commit_group;" ::: "memory")
#define CP_WAIT1()   asm volatile("cp.async.wait_group 1;" ::: "memory")
#define CP_WAIT2()   asm volatile("cp.async.wait_group 2;" ::: "memory")

// ---------------- scatter pooling (last token index wins) ----------------
__global__ void k_init_winner() {
    int w = blockIdx.x * blockDim.x + threadIdx.x;
    if (w < W_NUM) g_winner[w] = -1;
}
__global__ void k_scatter(const int* __restrict__ wmask) {
    int l = blockIdx.x * blockDim.x + threadIdx.x;
    if (l < L_TOK) {
        int v = wmask[l];
        if (v > 0 && v - 1 < W_NUM) atomicMax(&g_winner[v - 1], l);
    }
}
__global__ void k_build_we_h(const float* __restrict__ tok_embs) {
    int w = blockIdx.x;
    int src = g_winner[w];
    __half* dst = &g_weh[w * H_DIM];
    if (src >= 0) {
        const float* s = &tok_embs[(size_t)src * H_DIM];
        for (int h = threadIdx.x; h < H_DIM; h += blockDim.x) dst[h] = __float2half(s[h]);
    } else {
        for (int h = threadIdx.x; h < H_DIM; h += blockDim.x) dst[h] = __float2half(0.0f);
    }
}

// ---------------- transpose: fp32 src[K][N] -> half dst[N][K] -------------
__global__ void k_transpose_h(const float* __restrict__ src, __half* __restrict__ dst,
                              int K, int N) {
    __shared__ float tl[32][33];
    int n0 = blockIdx.x * 32, k0 = blockIdx.y * 32;
    for (int dy = threadIdx.y; dy < 32; dy += 8)
        tl[dy][threadIdx.x] = src[(size_t)(k0 + dy) * N + n0 + threadIdx.x];
    __syncthreads();
    for (int dy = threadIdx.y; dy < 32; dy += 8)
        dst[(size_t)(n0 + dy) * K + k0 + threadIdx.x] = __float2half(tl[threadIdx.x][dy]);
}

// ---------------- SIMT fp32 GEMM (small label-side GEMMs only) ------------
__global__ void k_gemm_bias(const float* __restrict__ A, int lda,
                            const float* __restrict__ B, int ldb,
                            const float* __restrict__ bias,
                            float* __restrict__ C, int ldc, int K) {
    __shared__ float As[16][64];
    __shared__ float Bs[16][64];
    const int tid = threadIdx.x;
    const int tx = tid & 15;
    const int ty = tid >> 4;
    const int mbase = blockIdx.x * 64;
    const int nbase = blockIdx.y * 64;

    float acc[4][4] = {};
    const int lw = tid >> 2, lkq = tid & 3;
    const int lkk = tid >> 4, lj4 = tid & 15;

    for (int k0 = 0; k0 < K; k0 += 16) {
        float4 va = *reinterpret_cast<const float4*>(&A[(size_t)(mbase + lw) * lda + k0 + lkq * 4]);
        As[lkq * 4 + 0][lw] = va.x;
        As[lkq * 4 + 1][lw] = va.y;
        As[lkq * 4 + 2][lw] = va.z;
        As[lkq * 4 + 3][lw] = va.w;
        *reinterpret_cast<float4*>(&Bs[lkk][lj4 * 4]) =
            *reinterpret_cast<const float4*>(&B[(size_t)(k0 + lkk) * ldb + nbase + lj4 * 4]);
        __syncthreads();
#pragma unroll
        for (int kk = 0; kk < 16; kk++) {
            float4 a4 = *reinterpret_cast<const float4*>(&As[kk][ty * 4]);
            float4 b4 = *reinterpret_cast<const float4*>(&Bs[kk][tx * 4]);
            float a[4] = {a4.x, a4.y, a4.z, a4.w};
            float b[4] = {b4.x, b4.y, b4.z, b4.w};
#pragma unroll
            for (int i = 0; i < 4; i++)
#pragma unroll
                for (int j = 0; j < 4; j++)
                    acc[i][j] = fmaf(a[i], b[j], acc[i][j]);
        }
        __syncthreads();
    }
#pragma unroll
    for (int j = 0; j < 4; j++) {
        int col = nbase + tx * 4 + j;
        float bv = bias ? bias[col] : 0.0f;
#pragma unroll
        for (int i = 0; i < 4; i++) {
            int row = mbase + ty * 4 + i;
            C[(size_t)row * ldc + col] = acc[i][j] + bv;
        }
    }
}

// ================== generic fp16 mma GEMM (prologue) ======================
// C[M,N] = A[M,K]h @ B[N,K]h^T + bias (half C). BM=BN=128, BK=16,
// 4-stage cp.async, K fixed at 768.
#define PLDH 24
#define PKT  48
#define PA_STAGE_B (128 * PLDH * 2)   // 6144 bytes
#define PSMEM_SZ (8 * PA_STAGE_B)     // 49152 bytes

__global__ void __launch_bounds__(256)
k_gemm_h(const __half* __restrict__ A, int lda,
         const __half* __restrict__ B, int ldb,
         const float* __restrict__ bias,
         __half* __restrict__ C, int ldc) {
    extern __shared__ char psm[];
    __half* Ash = reinterpret_cast<__half*>(psm);
    __half* Bsh = reinterpret_cast<__half*>(psm + 4 * PA_STAGE_B);
    const uint32_t sbA = smem_u32(Ash);
    const uint32_t sbB = smem_u32(Bsh);

    const int tid = threadIdx.x;
    const int lane = tid & 31, wid = tid >> 5;
    const int wm = wid & 3, wn = wid >> 2;
    const int qr = lane >> 2, qc = lane & 3;
    const int mb = blockIdx.x * 128;
    const int nb = blockIdx.y * 128;
    const int l_row = tid >> 1, l_ch = tid & 1;

    float cf[2][8][4];
#pragma unroll
    for (int mt = 0; mt < 2; mt++)
#pragma unroll
        for (int nt = 0; nt < 8; nt++)
#pragma unroll
            for (int r = 0; r < 4; r++) cf[mt][nt][r] = 0.0f;

#pragma unroll
    for (int p = 0; p < 3; p++) {
        const int k0 = p * 16;
        cpasync16(sbA + (uint32_t)(p * PA_STAGE_B + l_row * (PLDH * 2) + l_ch * 16),
                  &A[(size_t)(mb + l_row) * lda + k0 + l_ch * 8]);
        cpasync16(sbB + (uint32_t)(p * PA_STAGE_B + l_row * (PLDH * 2) + l_ch * 16),
                  &B[(size_t)(nb + l_row) * ldb + k0 + l_ch * 8]);
        CP_COMMIT();
    }

    for (int kt = 0; kt < PKT; kt++) {
        CP_WAIT2();
        __syncthreads();
        const int bi = kt & 3;
        const __half* Asb = Ash + bi * (128 * PLDH);
        const __half* Bsb = Bsh + bi * (128 * PLDH);
        uint32_t a[2][4];
#pragma unroll
        for (int mt = 0; mt < 2; mt++) {
            int rb = wm * 32 + mt * 16 + qr;
            a[mt][0] = *reinterpret_cast<const uint32_t*>(&Asb[rb * PLDH + 2 * qc]);
            a[mt][1] = *reinterpret_cast<const uint32_t*>(&Asb[(rb + 8) * PLDH + 2 * qc]);
            a[mt][2] = *reinterpret_cast<const uint32_t*>(&Asb[rb * PLDH + 2 * qc + 8]);
            a[mt][3] = *reinterpret_cast<const uint32_t*>(&Asb[(rb + 8) * PLDH + 2 * qc + 8]);
        }
#pragma unroll
        for (int nt = 0; nt < 8; nt++) {
            int ncol = wn * 64 + nt * 8 + qr;
            uint32_t b0 = *reinterpret_cast<const uint32_t*>(&Bsb[ncol * PLDH + 2 * qc]);
            uint32_t b1 = *reinterpret_cast<const uint32_t*>(&Bsb[ncol * PLDH + 2 * qc + 8]);
            mma_f16(cf[0][nt], a[0], b0, b1);
            mma_f16(cf[1][nt], a[1], b0, b1);
        }
        const int kn = kt + 3;
        if (kn < PKT) {
            const int st = kn & 3;
            const int k0 = kn * 16;
            cpasync16(sbA + (uint32_t)(st * PA_STAGE_B + l_row * (PLDH * 2) + l_ch * 16),
                      &A[(size_t)(mb + l_row) * lda + k0 + l_ch * 8]);
            cpasync16(sbB + (uint32_t)(st * PA_STAGE_B + l_row * (PLDH * 2) + l_ch * 16),
                      &B[(size_t)(nb + l_row) * ldb + k0 + l_ch * 8]);
        }
        CP_COMMIT();
    }

#pragma unroll
    for (int mt = 0; mt < 2; mt++)
#pragma unroll
        for (int nt = 0; nt < 8; nt++) {
            const int gcol = nb + wn * 64 + nt * 8 + 2 * qc;
            const int r0 = mb + wm * 32 + mt * 16 + qr;
            const float bv0 = bias ? bias[gcol] : 0.0f;
            const float bv1 = bias ? bias[gcol + 1] : 0.0f;
            *reinterpret_cast<__half2*>(&C[(size_t)r0 * ldc + gcol]) =
                __floats2half2_rn(cf[mt][nt][0] + bv0, cf[mt][nt][1] + bv1);
            *reinterpret_cast<__half2*>(&C[(size_t)(r0 + 8) * ldc + gcol]) =
                __floats2half2_rn(cf[mt][nt][2] + bv0, cf[mt][nt][3] + bv1);
        }
}

// ================== main fused fp16 mma kernel ============================
// Grid (8, 64). Block 256 (8 warps, 4m x 2n). BM=128, BN=128, BK=32,
// 3-stage cp.async + smem At prefetch. B = shared half(W1p^T) (L2-resident);
// per-c scale lb1 applied to A fragments in registers (HMUL2).
#define BM 128
#define BN 128
#define BK 32
#define NJT 6
#define KTILES 24
#define LDH 40                      // 32 + 8 pad halves; 80B rows, conflict-free
#define A_STAGE_B (BM * LDH * 2)    // 10240 bytes
#define LDAT 136                    // At row: 128 + 8 pad halves = 272 B (conflict-free)

#define O_BS   (3 * A_STAGE_B)                 // 30720
#define O_ATS  (O_BS + 3 * A_STAGE_B)          // 61440
#define O_ALS  (O_ATS + BM * LDAT * 2)         // 96256
#define O_W2S  (O_ALS + H_DIM * 4)             // 99328
#define O_SCR  (O_W2S + 3 * H_DIM * 4)         // 108544
#define O_LBS  (O_SCR + BM * 3 * 4)            // 110080
#define SMEM_SZ (O_LBS + H_DIM * 2)            // 111616 bytes -> 2 blocks/SM

__global__ void __launch_bounds__(256, 2)
k_main_mma(const __half* __restrict__ t01h,   // (1024, 1536); t1 at col 768
           const __half* __restrict__ Bh,     // (768 j, 768 k) half(W1p^T), shared
           const __half* __restrict__ Ath,    // (1024, 768) half
           const float* __restrict__ lb,      // (64, 1536)
           const float* __restrict__ Al,      // (64, 768)
           const float* __restrict__ W2,      // (768, 3)
           const float* __restrict__ b2,
           float* __restrict__ out) {         // (1024, 64, 3)
    extern __shared__ char smc[];
    __half* Ash = reinterpret_cast<__half*>(smc);
    __half* Bsh = reinterpret_cast<__half*>(smc + O_BS);
    __half* Ats = reinterpret_cast<__half*>(smc + O_ATS);
    float* als = reinterpret_cast<float*>(smc + O_ALS);
    float* w2s = reinterpret_cast<float*>(smc + O_W2S);
    float* scr = reinterpret_cast<float*>(smc + O_SCR);
    __half* lbsh = reinterpret_cast<__half*>(smc + O_LBS);
    const uint32_t sbA = smem_u32(Ash);
    const uint32_t sbB = smem_u32(Bsh);
    const uint32_t sbT = smem_u32(Ats);

    const int tid = threadIdx.x;
    const int lane = tid & 31, wid = tid >> 5;
    const int wm = wid & 3, wn = wid >> 2;
    const int qr = lane >> 2, qc = lane & 3;
    const int c = blockIdx.y;
    const int wbase = blockIdx.x * BM;

    for (int i = tid; i < H_DIM; i += 256) {
        als[i] = Al[c * H_DIM + i];
        lbsh[i] = __float2half(lb[(size_t)c * TH_DIM + H_DIM + i]);
    }
    for (int i = tid; i < 3 * H_DIM; i += 256) w2s[i] = W2[i];
    for (int i = tid; i < BM * 3; i += 256) scr[i] = 0.0f;
    __syncthreads();

    const uint32_t* lbs2 = reinterpret_cast<const uint32_t*>(lbsh);
    const __half* A0 = t01h + H_DIM;    // t1 columns

    float sc[4][3];
#pragma unroll
    for (int i = 0; i < 4; i++)
#pragma unroll
        for (int k = 0; k < 3; k++) sc[i][k] = 0.0f;

    for (int jt = 0; jt < NJT; jt++) {
        const int jb = jt * BN;
        float cf[2][8][4];
#pragma unroll
        for (int mt = 0; mt < 2; mt++)
#pragma unroll
            for (int nt = 0; nt < 8; nt++)
#pragma unroll
                for (int r = 0; r < 4; r++) cf[mt][nt][r] = 0.0f;

        // ---- prologue: k-tiles 0..1 into stages 0..1 (2 chunks/thread/matrix) ----
#pragma unroll
        for (int p = 0; p < 2; p++) {
            const int k0 = p * BK;
#pragma unroll
            for (int i = 0; i < 2; i++) {
                int idx = tid + 256 * i;
                int row = idx >> 2, ch = idx & 3;
                cpasync16(sbA + (uint32_t)(p * A_STAGE_B + row * (LDH * 2) + ch * 16),
                          &A0[(size_t)(wbase + row) * TH_DIM + k0 + ch * 8]);
                cpasync16(sbB + (uint32_t)(p * A_STAGE_B + row * (LDH * 2) + ch * 16),
                          &Bh[(size_t)(jb + row) * H_DIM + k0 + ch * 8]);
            }
            CP_COMMIT();
        }

        for (int kt = 0; kt < KTILES; kt++) {
            CP_WAIT1();
            __syncthreads();
            const int bi = kt % 3;
            const __half* Asb = Ash + bi * (A_STAGE_B / 2);
            const __half* Bsb = Bsh + bi * (A_STAGE_B / 2);
#pragma unroll
            for (int ks = 0; ks < 2; ks++) {
                const int ko = ks * 16;
                const int kb2 = (kt * BK + ko) >> 1;
                const uint32_t sA = lbs2[kb2 + qc];
                const uint32_t sB = lbs2[kb2 + qc + 4];
                uint32_t a[2][4];
#pragma unroll
                for (int mt = 0; mt < 2; mt++) {
                    int rb = wm * 32 + mt * 16 + qr;
                    a[mt][0] = hmul2u(*reinterpret_cast<const uint32_t*>(&Asb[rb * LDH + ko + 2 * qc]), sA);
                    a[mt][1] = hmul2u(*reinterpret_cast<const uint32_t*>(&Asb[(rb + 8) * LDH + ko + 2 * qc]), sA);
                    a[mt][2] = hmul2u(*reinterpret_cast<const uint32_t*>(&Asb[rb * LDH + ko + 2 * qc + 8]), sB);
                    a[mt][3] = hmul2u(*reinterpret_cast<const uint32_t*>(&Asb[(rb + 8) * LDH + ko + 2 * qc + 8]), sB);
                }
#pragma unroll
                for (int nt = 0; nt < 8; nt++) {
                    int ncol = wn * 64 + nt * 8 + qr;
                    uint32_t b0 = *reinterpret_cast<const uint32_t*>(&Bsb[ncol * LDH + ko + 2 * qc]);
                    uint32_t b1 = *reinterpret_cast<const uint32_t*>(&Bsb[ncol * LDH + ko + 2 * qc + 8]);
                    mma_f16(cf[0][nt], a[0], b0, b1);
                    mma_f16(cf[1][nt], a[1], b0, b1);
                }
            }
            // ---- issue k-tile kt+2 + one At chunk per thread (kts 0..7) ----
            const int kn = kt + 2;
            if (kn < KTILES) {
                const int st = kn % 3;
                const int k0 = kn * BK;
#pragma unroll
                for (int i = 0; i < 2; i++) {
                    int idx = tid + 256 * i;
                    int row = idx >> 2, ch = idx & 3;
                    cpasync16(sbA + (uint32_t)(st * A_STAGE_B + row * (LDH * 2) + ch * 16),
                              &A0[(size_t)(wbase + row) * TH_DIM + k0 + ch * 8]);
                    cpasync16(sbB + (uint32_t)(st * A_STAGE_B + row * (LDH * 2) + ch * 16),
                              &Bh[(size_t)(jb + row) * H_DIM + k0 + ch * 8]);
                }
            }
            if (kt < 8) {
                // At j-tile: 128 rows x 16 chunks of 16B; 256 chunks per kt
                int cidx = tid + 256 * kt;
                int row = cidx >> 4, ch = cidx & 15;
                cpasync16(sbT + (uint32_t)(row * (LDAT * 2) + ch * 16),
                          &Ath[(size_t)(wbase + row) * H_DIM + jb + ch * 8]);
            }
            CP_COMMIT();
        }

        // ---- fused epilogue for this j-tile (At from smem) ----
#pragma unroll
        for (int mt = 0; mt < 2; mt++) {
#pragma unroll
            for (int nt = 0; nt < 8; nt++) {
                const int lcol = wn * 64 + nt * 8 + 2 * qc;
                const int gcol = jb + lcol;
                const int lr0 = wm * 32 + mt * 16 + qr;
                float2 at0 = __half22float2(
                    *reinterpret_cast<const __half2*>(&Ats[lr0 * LDAT + lcol]));
                float2 at1 = __half22float2(
                    *reinterpret_cast<const __half2*>(&Ats[(lr0 + 8) * LDAT + lcol]));
                const float al0 = als[gcol], al1 = als[gcol + 1];
                const float wa0 = w2s[gcol * 3 + 0], wa1 = w2s[gcol * 3 + 1], wa2 = w2s[gcol * 3 + 2];
                const float wb0 = w2s[gcol * 3 + 3], wb1 = w2s[gcol * 3 + 4], wb2 = w2s[gcol * 3 + 5];
                const float h00 = fmaxf(cf[mt][nt][0] + at0.x + al0, 0.0f);
                const float h01 = fmaxf(cf[mt][nt][1] + at0.y + al1, 0.0f);
                const float h10 = fmaxf(cf[mt][nt][2] + at1.x + al0, 0.0f);
                const float h11 = fmaxf(cf[mt][nt][3] + at1.y + al1, 0.0f);
                sc[mt * 2 + 0][0] += h00 * wa0 + h01 * wb0;
                sc[mt * 2 + 0][1] += h00 * wa1 + h01 * wb1;
                sc[mt * 2 + 0][2] += h00 * wa2 + h01 * wb2;
                sc[mt * 2 + 1][0] += h10 * wa0 + h11 * wb0;
                sc[mt * 2 + 1][1] += h10 * wa1 + h11 * wb1;
                sc[mt * 2 + 1][2] += h10 * wa2 + h11 * wb2;
            }
        }
        __syncthreads();   // all epilogue reads of Ats done before next j-tile overwrites
    }

    // ---- reduce over qc lanes, then across n-warps via shared atomics ----
#pragma unroll
    for (int i = 0; i < 4; i++)
#pragma unroll
        for (int k = 0; k < 3; k++) {
            float v = sc[i][k];
            v += __shfl_xor_sync(0xffffffffu, v, 1);
            v += __shfl_xor_sync(0xffffffffu, v, 2);
            sc[i][k] = v;
        }
    if (qc == 0) {
#pragma unroll
        for (int i = 0; i < 4; i++) {
            int rl = wm * 32 + (i >> 1) * 16 + (i & 1) * 8 + qr;
            atomicAdd(&scr[rl * 3 + 0], sc[i][0]);
            atomicAdd(&scr[rl * 3 + 1], sc[i][1]);
            atomicAdd(&scr[rl * 3 + 2], sc[i][2]);
        }
    }
    __syncthreads();
    if (tid < BM) {
        const int row = wbase + tid;
        float* o = &out[(size_t)row * (C_NUM * 3) + c * 3];
        o[0] = scr[tid * 3 + 0] + __ldg(&b2[0]);
        o[1] = scr[tid * 3 + 1] + __ldg(&b2[1]);
        o[2] = scr[tid * 3 + 2] + __ldg(&b2[2]);
    }
}

// ---------------- launch ---------------------------------------------------
extern "C" void kernel_launch(void* const* d_in, const int* in_sizes, int n_in,
                              void* d_out, int out_size) {
    const float* tok_embs   = (const float*)d_in[0];   // (2048, 768)
    const int*   wmask      = (const int*)  d_in[1];   // (2048,)
    const float* label_embs = (const float*)d_in[3];   // (64, 768)
    const float* W_tok      = (const float*)d_in[4];   // (768, 1536)
    const float* b_tok      = (const float*)d_in[5];   // (1536,)
    const float* W_lab      = (const float*)d_in[6];   // (768, 1536)
    const float* b_lab      = (const float*)d_in[7];   // (1536,)
    const float* W1         = (const float*)d_in[8];   // (2304, 768)
    const float* b1         = (const float*)d_in[9];   // (768,)
    const float* W2         = (const float*)d_in[10];  // (768, 3)
    const float* b2         = (const float*)d_in[11];  // (3,)
    float* out = (float*)d_out;                        // (1024, 64, 3)

    float *lbp, *Al;
    __half *weh, *WtokT, *W1tT, *W1pTh, *t01h, *Ath;
    cudaGetSymbolAddress((void**)&lbp,   g_lb);
    cudaGetSymbolAddress((void**)&Ath,   g_Ath);
    cudaGetSymbolAddress((void**)&Al,    g_Al);
    cudaGetSymbolAddress((void**)&weh,   g_weh);
    cudaGetSymbolAddress((void**)&WtokT, g_WtokT);
    cudaGetSymbolAddress((void**)&W1tT,  g_W1tT);
    cudaGetSymbolAddress((void**)&W1pTh, g_W1pTh);
    cudaGetSymbolAddress((void**)&t01h,  g_t01h);

    // idempotent, deterministic — no static guards (harness rule)
    cudaFuncSetAttribute(k_main_mma, cudaFuncAttributeMaxDynamicSharedMemorySize, SMEM_SZ);
    cudaFuncSetAttribute(k_gemm_h, cudaFuncAttributeMaxDynamicSharedMemorySize, PSMEM_SZ);

    // 0) weight prep (independent): half transposes of W_tok, W1_t, W1_p
    k_transpose_h<<<dim3(TH_DIM / 32, H_DIM / 32), dim3(32, 8)>>>(
        W_tok, WtokT, H_DIM, TH_DIM);
    k_transpose_h<<<dim3(H_DIM / 32, H_DIM / 32), dim3(32, 8)>>>(
        W1, W1tT, H_DIM, H_DIM);
    k_transpose_h<<<dim3(H_DIM / 32, H_DIM / 32), dim3(32, 8)>>>(
        W1 + (size_t)2 * H_DIM * H_DIM, W1pTh, H_DIM, H_DIM);

    // 1) scatter pooling (last token index wins per word), half output
    k_init_winner<<<(W_NUM + 255) / 256, 256>>>();
    k_scatter<<<(L_TOK + 255) / 256, 256>>>(wmask);
    k_build_we_h<<<W_NUM, 256>>>(tok_embs);

    // 2) lb = label_embs @ W_lab + b_lab (64 x 1536, fp32 SIMT)
    k_gemm_bias<<<dim3(1, TH_DIM / 64), 256>>>(
        label_embs, H_DIM, W_lab, TH_DIM, b_lab, lbp, TH_DIM, H_DIM);

    // 3) t01h = half(weh @ W_tok + b_tok)   (1024 x 1536, fp16 mma)
    k_gemm_h<<<dim3(W_NUM / 128, TH_DIM / 128), 256, PSMEM_SZ>>>(
        weh, H_DIM, WtokT, H_DIM, b_tok, t01h, TH_DIM);

    // 4) Ath = half(t0h @ W1_t + b1)        (1024 x 768, fp16 mma)
    k_gemm_h<<<dim3(W_NUM / 128, H_DIM / 128), 256, PSMEM_SZ>>>(
        t01h, TH_DIM, W1tT, H_DIM, b1, Ath, H_DIM);

    // 5) Al = lb0 @ W1_l                    (64 x 768, fp32 SIMT)
    k_gemm_bias<<<dim3(1, H_DIM / 64), 256>>>(
        lbp, TH_DIM, W1 + (size_t)H_DIM * H_DIM, H_DIM, nullptr, Al, H_DIM, H_DIM);

    // 6) fused fp16 mma prod-GEMM + relu + W2 contraction -> scores
    k_main_mma<<<dim3(W_NUM / BM, C_NUM), 256, SMEM_SZ>>>(
        t01h, W1pTh, Ath, lbp, Al, W2, b2, out);

    (void)in_sizes; (void)n_in; (void)out_size;
}